// round 13
// baseline (speedup 1.0000x reference)
#include <cuda_runtime.h>
#include <cuda_bf16.h>
#include <cuda_fp16.h>
#include <cstdint>

typedef __nv_bfloat16 bf16;

#define BATCH 2
#define SEQ 2048
#define IN_DIM 1024
#define HID_DIM 1024
#define NHEAD 16
#define HDIM 64
#define KDIM 1024
#define MROWS 4096

// ---------------------------------------------------------------------------
// Scratch (__device__ globals; allocation-free rule)
// ---------------------------------------------------------------------------
__device__ bf16 g_qhi[MROWS * KDIM], g_qlo[MROWS * KDIM];
__device__ bf16 g_khi[MROWS * KDIM], g_klo[MROWS * KDIM];
__device__ bf16 g_vhi[MROWS * KDIM], g_vlo[MROWS * KDIM];
__device__ bf16 g_WqThi[HID_DIM * KDIM], g_WqTlo[HID_DIM * KDIM];
__device__ bf16 g_WkThi[HDIM * KDIM],   g_WkTlo[HDIM * KDIM];
__device__ bf16 g_WvThi[HDIM * KDIM],   g_WvTlo[HDIM * KDIM];
__device__ bf16 g_WoThi[IN_DIM * KDIM], g_WoTlo[IN_DIM * KDIM];
// projected fp16 operands for attention (all single fp16): Q scaled by 1/32
__device__ __half g_qPhi[MROWS * HID_DIM];
__device__ __half g_kPhi[MROWS * HDIM];
__device__ __half g_vPhi[MROWS * HDIM];
// attention output, bf16 split (A operand of O-projection)
__device__ bf16 g_ohi[MROWS * HID_DIM], g_olo[MROWS * HID_DIM];

// ---------------------------------------------------------------------------
// PTX helpers (all sm_80-era; legal in family-generic PTX)
// ---------------------------------------------------------------------------
__device__ __forceinline__ uint32_t smem_u32(const void* p) {
    uint32_t a;
    asm("{ .reg .u64 t; cvta.to.shared.u64 t, %1; cvt.u32.u64 %0, t; }"
        : "=r"(a) : "l"(p));
    return a;
}
__device__ __forceinline__ void ldsm_x4(uint32_t* r, uint32_t addr) {
    asm volatile("ldmatrix.sync.aligned.m8n8.x4.shared.b16 {%0,%1,%2,%3}, [%4];"
                 : "=r"(r[0]), "=r"(r[1]), "=r"(r[2]), "=r"(r[3]) : "r"(addr));
}
__device__ __forceinline__ void ldsm_x4_t(uint32_t* r, uint32_t addr) {
    asm volatile("ldmatrix.sync.aligned.m8n8.x4.trans.shared.b16 {%0,%1,%2,%3}, [%4];"
                 : "=r"(r[0]), "=r"(r[1]), "=r"(r[2]), "=r"(r[3]) : "r"(addr));
}
__device__ __forceinline__ void mma_bf16(float* d, const uint32_t* a,
                                         const uint32_t* b) {
    asm volatile(
        "mma.sync.aligned.m16n8k16.row.col.f32.bf16.bf16.f32 "
        "{%0,%1,%2,%3}, {%4,%5,%6,%7}, {%8,%9}, {%0,%1,%2,%3};"
        : "+f"(d[0]), "+f"(d[1]), "+f"(d[2]), "+f"(d[3])
        : "r"(a[0]), "r"(a[1]), "r"(a[2]), "r"(a[3]), "r"(b[0]), "r"(b[1]));
}
__device__ __forceinline__ void mma_f16(float* d, const uint32_t* a,
                                        const uint32_t* b) {
    asm volatile(
        "mma.sync.aligned.m16n8k16.row.col.f32.f16.f16.f32 "
        "{%0,%1,%2,%3}, {%4,%5,%6,%7}, {%8,%9}, {%0,%1,%2,%3};"
        : "+f"(d[0]), "+f"(d[1]), "+f"(d[2]), "+f"(d[3])
        : "r"(a[0]), "r"(a[1]), "r"(a[2]), "r"(a[3]), "r"(b[0]), "r"(b[1]));
}
__device__ __forceinline__ void cp16(uint32_t smem, const void* g) {
    asm volatile("cp.async.cg.shared.global [%0], [%1], 16;"
                 :: "r"(smem), "l"(g));
}
__device__ __forceinline__ void cp_commit() {
    asm volatile("cp.async.commit_group;" ::: "memory");
}
__device__ __forceinline__ void cp_wait1() {
    asm volatile("cp.async.wait_group 1;" ::: "memory");
}
__device__ __forceinline__ void cp_wait0() {
    asm volatile("cp.async.wait_group 0;" ::: "memory");
}
__device__ __forceinline__ void split_pack(float e, float o,
                                           uint32_t& hp, uint32_t& lp) {
    const bf16 he = __float2bfloat16(e), ho = __float2bfloat16(o);
    const bf16 le = __float2bfloat16(e - __bfloat162float(he));
    const bf16 lo2 = __float2bfloat16(o - __bfloat162float(ho));
    __nv_bfloat162 H(he, ho), L(le, lo2);
    hp = *reinterpret_cast<uint32_t*>(&H);
    lp = *reinterpret_cast<uint32_t*>(&L);
}
__device__ __forceinline__ uint32_t pack_h2(float e, float o) {
    __half2 P(__float2half_rn(e), __float2half_rn(o));
    return *reinterpret_cast<uint32_t*>(&P);
}
__device__ __forceinline__ uint32_t pack_b2(float e, float o) {
    __nv_bfloat162 P(__float2bfloat16(e), __float2bfloat16(o));
    return *reinterpret_cast<uint32_t*>(&P);
}

// ---------------------------------------------------------------------------
// Prep kernels
// ---------------------------------------------------------------------------
__device__ __forceinline__ void tsw_body(const float* W, bf16* Thi, bf16* Tlo,
                                         int K, int N)
{
    __shared__ float t[32][33];
    const int n0 = blockIdx.x * 32, k0 = blockIdx.y * 32;
    const int tx = threadIdx.x, ty = threadIdx.y;
#pragma unroll
    for (int i = 0; i < 32; i += 8)
        t[ty + i][tx] = W[(size_t)(k0 + ty + i) * N + n0 + tx];
    __syncthreads();
#pragma unroll
    for (int i = 0; i < 32; i += 8) {
        const float v = t[tx][ty + i];
        const bf16 h = __float2bfloat16(v);
        const bf16 l = __float2bfloat16(v - __bfloat162float(h));
        const size_t idx = (size_t)(n0 + ty + i) * K + k0 + tx;
        Thi[idx] = h;
        Tlo[idx] = l;
    }
}
struct TW2 { const float* W[2]; bf16* Thi[2]; bf16* Tlo[2]; };
__global__ void transpose_split_w2(TW2 a, int K, int N)
{
    const int z = blockIdx.z;
    tsw_body(a.W[z], a.Thi[z], a.Tlo[z], K, N);
}

// vectorized hi/lo split: 8 fp32 in (2x float4), uint4 hi + uint4 lo out
struct SR3 { const float4* X[3]; uint4* hi[3]; uint4* lo[3]; };
__global__ void split_rows3(SR3 a, int n8)
{
    const int z = blockIdx.y;
    const int i = blockIdx.x * blockDim.x + threadIdx.x;
    if (i < n8) {
        const float4 v0 = a.X[z][2 * i];
        const float4 v1 = a.X[z][2 * i + 1];
        const bf16 h0 = __float2bfloat16(v0.x), h1 = __float2bfloat16(v0.y);
        const bf16 h2 = __float2bfloat16(v0.z), h3 = __float2bfloat16(v0.w);
        const bf16 h4 = __float2bfloat16(v1.x), h5 = __float2bfloat16(v1.y);
        const bf16 h6 = __float2bfloat16(v1.z), h7 = __float2bfloat16(v1.w);
        uint4 H, L;
        H.x = pack_b2(v0.x, v0.y);
        H.y = pack_b2(v0.z, v0.w);
        H.z = pack_b2(v1.x, v1.y);
        H.w = pack_b2(v1.z, v1.w);
        L.x = pack_b2(v0.x - __bfloat162float(h0), v0.y - __bfloat162float(h1));
        L.y = pack_b2(v0.z - __bfloat162float(h2), v0.w - __bfloat162float(h3));
        L.z = pack_b2(v1.x - __bfloat162float(h4), v1.y - __bfloat162float(h5));
        L.w = pack_b2(v1.z - __bfloat162float(h6), v1.w - __bfloat162float(h7));
        a.hi[z][i] = H;
        a.lo[z][i] = L;
    }
}

// ---------------------------------------------------------------------------
// cp.async double-buffered mma.sync bf16 3-term split GEMM core.
// K-chunk 32 (ROWB=80B rows; r*20 mod 32 -> conflict-free ldmatrix), 2 stages
// = 40KB smem for 128x128 -> 2 CTAs/SM.
// EPI=0: fp32 C=acc+bias.  EPI=2: fp16 hi-only Chi=(acc+bias)*scale.
// ---------------------------------------------------------------------------
template <int BM, int BN, int EPI>
__device__ __forceinline__ void gemm_core(
    const bf16* Ahi, const bf16* Alo, const bf16* Bhi, const bf16* Blo,
    const float* bias, float* C, __half* Chi,
    float scale, int Ntot, int m0, int n0, char* smem)
{
    constexpr int MF = BM / 64;
    constexpr int WN = BN / 2;
    constexpr int NF = WN / 8;
    constexpr uint32_t ROWB = 80;                  // 32 bf16 = 64B data + 16B pad
    constexpr uint32_t OAL = BM * ROWB;
    constexpr uint32_t OBH = 2 * BM * ROWB;
    constexpr uint32_t OBL = OBH + BN * ROWB;
    constexpr uint32_t STAGE = (2 * BM + 2 * BN) * ROWB;
    constexpr int NCH = KDIM / 32;                 // 32 chunks

    const uint32_t uS = smem_u32(smem);
    const int tid = threadIdx.x;
    const int wid = tid >> 5, lane = tid & 31;
    const int warp_m = wid & 3, warp_n = wid >> 2;
    const int lrow = lane & 15;
    const int lcol = (lane >> 4) * 8;

    const bf16* a_hi = Ahi + (size_t)m0 * KDIM;
    const bf16* a_lo = Alo + (size_t)m0 * KDIM;
    const bf16* b_hi = Bhi + (size_t)n0 * KDIM;
    const bf16* b_lo = Blo + (size_t)n0 * KDIM;

    auto issue = [&](int ch, int buf) {
        const int k0 = ch * 32;
        const uint32_t base = uS + (uint32_t)buf * STAGE;
#pragma unroll
        for (int i = tid; i < BM * 4; i += 256) {
            const int r = i >> 2, c = i & 3;
            const uint32_t so = (uint32_t)r * ROWB + c * 16;
            const size_t g = (size_t)r * KDIM + k0 + c * 8;
            cp16(base + so, a_hi + g);
            cp16(base + OAL + so, a_lo + g);
        }
#pragma unroll
        for (int i = tid; i < BN * 4; i += 256) {
            const int r = i >> 2, c = i & 3;
            const uint32_t so = (uint32_t)r * ROWB + c * 16;
            const size_t g = (size_t)r * KDIM + k0 + c * 8;
            cp16(base + OBH + so, b_hi + g);
            cp16(base + OBL + so, b_lo + g);
        }
    };

    float acc[MF][NF][4] = {};

    issue(0, 0);
    cp_commit();

    for (int ch = 0; ch < NCH; ch++) {
        if (ch + 1 < NCH) {
            issue(ch + 1, (ch + 1) & 1);
            cp_commit();
            cp_wait1();
        } else {
            cp_wait0();
        }
        __syncthreads();

        const uint32_t base = uS + (uint32_t)(ch & 1) * STAGE;
#pragma unroll
        for (int ks = 0; ks < 2; ks++) {
            const int kk = ks * 16 + lcol;
            uint32_t ah[MF][4], al[MF][4];
#pragma unroll
            for (int mf = 0; mf < MF; mf++) {
                const int row = warp_m * (BM / 4) + mf * 16 + lrow;
                const uint32_t off = (uint32_t)row * ROWB + kk * 2;
                ldsm_x4(ah[mf], base + off);
                ldsm_x4(al[mf], base + OAL + off);
            }
            uint32_t bh[NF][2], bl[NF][2];
#pragma unroll
            for (int p = 0; p < NF / 2; p++) {
                const int row = warp_n * WN + p * 16 + lrow;
                const uint32_t off = (uint32_t)row * ROWB + kk * 2;
                uint32_t r4[4];
                ldsm_x4(r4, base + OBH + off);
                bh[2 * p][0] = r4[0]; bh[2 * p][1] = r4[2];
                bh[2 * p + 1][0] = r4[1]; bh[2 * p + 1][1] = r4[3];
                ldsm_x4(r4, base + OBL + off);
                bl[2 * p][0] = r4[0]; bl[2 * p][1] = r4[2];
                bl[2 * p + 1][0] = r4[1]; bl[2 * p + 1][1] = r4[3];
            }
#pragma unroll
            for (int mf = 0; mf < MF; mf++)
#pragma unroll
                for (int nf = 0; nf < NF; nf++) {
                    mma_bf16(acc[mf][nf], ah[mf], bh[nf]);
                    mma_bf16(acc[mf][nf], ah[mf], bl[nf]);
                    mma_bf16(acc[mf][nf], al[mf], bh[nf]);
                }
        }
        __syncthreads();
    }

    const int gid = lane >> 2, t4 = lane & 3;
#pragma unroll
    for (int mf = 0; mf < MF; mf++) {
        const int row = m0 + warp_m * (BM / 4) + mf * 16 + gid;
#pragma unroll
        for (int nf = 0; nf < NF; nf++) {
            const int col = n0 + warp_n * WN + nf * 8 + t4 * 2;
            const float b0 = bias[col], b1 = bias[col + 1];
            if (EPI == 0) {
                float2 o0 = make_float2(acc[mf][nf][0] + b0, acc[mf][nf][1] + b1);
                float2 o1 = make_float2(acc[mf][nf][2] + b0, acc[mf][nf][3] + b1);
                *(float2*)(C + (size_t)row * Ntot + col) = o0;
                *(float2*)(C + (size_t)(row + 8) * Ntot + col) = o1;
            } else {
                *(uint32_t*)(Chi + (size_t)row * Ntot + col) =
                    pack_h2((acc[mf][nf][0] + b0) * scale,
                            (acc[mf][nf][1] + b1) * scale);
                *(uint32_t*)(Chi + (size_t)(row + 8) * Ntot + col) =
                    pack_h2((acc[mf][nf][2] + b0) * scale,
                            (acc[mf][nf][3] + b1) * scale);
            }
        }
    }
}

template <int BM, int BN, int EPI>
__global__ __launch_bounds__(256, 2) void gemm_mma(
    const bf16* __restrict__ Ahi, const bf16* __restrict__ Alo,
    const bf16* __restrict__ Bhi, const bf16* __restrict__ Blo,
    const float* __restrict__ bias, float* __restrict__ C,
    __half* __restrict__ Chi, float scale, int Ntot)
{
    extern __shared__ char smem[];
    gemm_core<BM, BN, EPI>(Ahi, Alo, Bhi, Blo, bias, C, Chi, scale, Ntot,
                           blockIdx.y * BM, blockIdx.x * BN, smem);
}

// ---------------------------------------------------------------------------
// Merged Q/K/V projection launch. grid (8, 32, 3):
//   z=0: Q-proj 128x128 tiles; z=1/2: K/V-proj 64x64 tiles (64 CTAs active)
// ---------------------------------------------------------------------------
struct ProjArgs {
    const bf16 *qAhi, *qAlo, *qBhi, *qBlo; const float* qb; __half* qC;
    const bf16 *kvAhi[2], *kvAlo[2], *kvBhi[2], *kvBlo[2];
    const float* kvb[2]; __half* kvC[2];
};
__global__ __launch_bounds__(256, 2) void gemm_proj_all(ProjArgs a)
{
    extern __shared__ char smem[];
    const int z = blockIdx.z;
    if (z == 0) {
        gemm_core<128, 128, 2>(a.qAhi, a.qAlo, a.qBhi, a.qBlo, a.qb,
                               nullptr, a.qC, 1.0f / 32.0f, HID_DIM,
                               blockIdx.y * 128, blockIdx.x * 128, smem);
    } else {
        const int id = blockIdx.y * 8 + blockIdx.x;   // 0..255
        if (id >= MROWS / 64) return;                 // 64 active
        const int s = z - 1;
        gemm_core<64, 64, 2>(a.kvAhi[s], a.kvAlo[s], a.kvBhi[s], a.kvBlo[s],
                             a.kvb[s], nullptr, a.kvC[s], 1.0f, HDIM,
                             id * 64, 0, smem);
    }
}

// ---------------------------------------------------------------------------
// Tensor-core MQA attention, pure single-fp16:
//   scores = Q·K (1 term);  PV = P·V (1 term)
// Block = 128 queries x (head, batch); 8 warps x 16-row strips; KBLK=64.
// cp.async double-buffered stages of {K, V}.
// ---------------------------------------------------------------------------
__global__ __launch_bounds__(256) void mqa_attn_mma(
    const __half* __restrict__ Qhi,
    const __half* __restrict__ Khi, const __half* __restrict__ Vhi,
    bf16* __restrict__ Ohi, bf16* __restrict__ Olo)
{
    constexpr uint32_t ROWB = 144;
    constexpr uint32_t ST0 = 128 * ROWB;          // end of Q region
    constexpr uint32_t STG = 128 * ROWB;          // stage {K, V}
    constexpr uint32_t VHI = 64 * ROWB;
    constexpr int NCH = SEQ / 64;                 // 32

    extern __shared__ char smc[];
    const uint32_t uS = smem_u32(smc);

    const int tid = threadIdx.x, wid = tid >> 5, lane = tid & 31;
    const int h = blockIdx.y, b = blockIdx.z;
    const int q0 = blockIdx.x * 128;
    const size_t qrow0 = (size_t)b * SEQ + q0;
    const int lrow = lane & 15;
    const int lcol = (lane >> 4) * 8;

    const __half* kh_g = Khi + (size_t)b * SEQ * HDIM;
    const __half* vh_g = Vhi + (size_t)b * SEQ * HDIM;

    auto issue = [&](int ch, int buf) {
        const int k0 = ch * 64;
        const uint32_t base = uS + ST0 + (uint32_t)buf * STG;
#pragma unroll
        for (int i = tid; i < 64 * 8; i += 256) {
            const int r = i >> 3, c8 = (i & 7) * 8;
            const uint32_t so = (uint32_t)r * ROWB + c8 * 2;
            const size_t g = (size_t)(k0 + r) * HDIM + c8;
            cp16(base + so, kh_g + g);
            cp16(base + VHI + so, vh_g + g);
        }
    };

    issue(0, 0);
    cp_commit();
    {
        const __half* qh_g = Qhi + qrow0 * HID_DIM + h * HDIM;
#pragma unroll
        for (int i = tid; i < 128 * 8; i += 256) {
            const int r = i >> 3, c8 = (i & 7) * 8;
            const uint32_t so = (uint32_t)r * ROWB + c8 * 2;
            *(uint4*)(smc + so) = *(const uint4*)(qh_g + (size_t)r * HID_DIM + c8);
        }
    }
    __syncthreads();
    uint32_t qh[4][4];
#pragma unroll
    for (int ks = 0; ks < 4; ks++) {
        const uint32_t off = (uint32_t)(wid * 16 + lrow) * ROWB + (ks * 16 + lcol) * 2;
        ldsm_x4(qh[ks], uS + off);
    }

    float m1 = -1e30f, m2 = -1e30f, lp1 = 0.0f, lp2 = 0.0f;
    float oacc[8][4] = {};

    for (int ch = 0; ch < NCH; ch++) {
        if (ch + 1 < NCH) {
            issue(ch + 1, (ch + 1) & 1);
            cp_commit();
            cp_wait1();
        } else {
            cp_wait0();
        }
        __syncthreads();

        const uint32_t base = uS + ST0 + (uint32_t)(ch & 1) * STG;

        // ---- scores: 16 rows x 64 keys; single term Q x K
        float sc[8][4] = {};
#pragma unroll
        for (int ks = 0; ks < 4; ks++) {
#pragma unroll
            for (int p = 0; p < 4; p++) {
                const uint32_t off =
                    (uint32_t)(p * 16 + lrow) * ROWB + (ks * 16 + lcol) * 2;
                uint32_t rh[4];
                ldsm_x4(rh, base + off);
                uint32_t b0[2] = {rh[0], rh[2]}, b1[2] = {rh[1], rh[3]};
                mma_f16(sc[2 * p], qh[ks], b0);
                mma_f16(sc[2 * p + 1], qh[ks], b1);
            }
        }

        // ---- online softmax in registers
        float mx1 = m1, mx2 = m2;
#pragma unroll
        for (int nf = 0; nf < 8; nf++) {
            mx1 = fmaxf(mx1, fmaxf(sc[nf][0], sc[nf][1]));
            mx2 = fmaxf(mx2, fmaxf(sc[nf][2], sc[nf][3]));
        }
        mx1 = fmaxf(mx1, __shfl_xor_sync(0xffffffffu, mx1, 1));
        mx1 = fmaxf(mx1, __shfl_xor_sync(0xffffffffu, mx1, 2));
        mx2 = fmaxf(mx2, __shfl_xor_sync(0xffffffffu, mx2, 1));
        mx2 = fmaxf(mx2, __shfl_xor_sync(0xffffffffu, mx2, 2));
        const float a1 = __expf(m1 - mx1);
        const float a2 = __expf(m2 - mx2);
        m1 = mx1; m2 = mx2;

        float s1 = 0.0f, s2 = 0.0f;
        uint32_t pr1[8], pr2[8];
#pragma unroll
        for (int nf = 0; nf < 8; nf++) {
            const float p0 = __expf(sc[nf][0] - mx1);
            const float p1 = __expf(sc[nf][1] - mx1);
            const float p2 = __expf(sc[nf][2] - mx2);
            const float p3 = __expf(sc[nf][3] - mx2);
            s1 += p0 + p1; s2 += p2 + p3;
            pr1[nf] = pack_h2(p0, p1);
            pr2[nf] = pack_h2(p2, p3);
        }
        lp1 = lp1 * a1 + s1;
        lp2 = lp2 * a2 + s2;
#pragma unroll
        for (int nf = 0; nf < 8; nf++) {
            oacc[nf][0] *= a1; oacc[nf][1] *= a1;
            oacc[nf][2] *= a2; oacc[nf][3] *= a2;
        }

        // ---- PV: single term (P fp16 x V fp16)
#pragma unroll
        for (int ks = 0; ks < 4; ks++) {
            uint32_t pa[4] = {pr1[2 * ks], pr2[2 * ks],
                              pr1[2 * ks + 1], pr2[2 * ks + 1]};
#pragma unroll
            for (int p = 0; p < 4; p++) {
                const uint32_t off =
                    (uint32_t)(ks * 16 + lrow) * ROWB + (p * 16 + lcol) * 2;
                uint32_t rh[4];
                ldsm_x4_t(rh, base + VHI + off);
                uint32_t b0[2] = {rh[0], rh[1]}, b1[2] = {rh[2], rh[3]};
                mma_f16(oacc[2 * p], pa, b0);
                mma_f16(oacc[2 * p + 1], pa, b1);
            }
        }
        __syncthreads();
    }

    lp1 += __shfl_xor_sync(0xffffffffu, lp1, 1);
    lp1 += __shfl_xor_sync(0xffffffffu, lp1, 2);
    lp2 += __shfl_xor_sync(0xffffffffu, lp2, 1);
    lp2 += __shfl_xor_sync(0xffffffffu, lp2, 2);
    const float i1 = 1.0f / lp1, i2 = 1.0f / lp2;

    const size_t row1 = qrow0 + wid * 16 + (lane >> 2);
    const size_t row2 = row1 + 8;
#pragma unroll
    for (int nf = 0; nf < 8; nf++) {
        const int col = h * HDIM + nf * 8 + (lane & 3) * 2;
        uint32_t hp, lp;
        split_pack(oacc[nf][0] * i1, oacc[nf][1] * i1, hp, lp);
        *(uint32_t*)(Ohi + row1 * HID_DIM + col) = hp;
        *(uint32_t*)(Olo + row1 * HID_DIM + col) = lp;
        split_pack(oacc[nf][2] * i2, oacc[nf][3] * i2, hp, lp);
        *(uint32_t*)(Ohi + row2 * HID_DIM + col) = hp;
        *(uint32_t*)(Olo + row2 * HID_DIM + col) = lp;
    }
}

static const int GEMM128_SMEM = 2 * (2 * 128 + 2 * 128) * 80;  // 81920
static const int ATTN_SMEM    = 128 * 144 + 2 * 128 * 144;     // 55296

// ---------------------------------------------------------------------------
// Launch
// ---------------------------------------------------------------------------
extern "C" void kernel_launch(void* const* d_in, const int* in_sizes, int n_in,
                              void* d_out, int out_size)
{
    const float* query = (const float*)d_in[0];
    const float* key   = (const float*)d_in[1];
    const float* value = (const float*)d_in[2];
    const float* Wq    = (const float*)d_in[3];
    const float* bq    = (const float*)d_in[4];
    const float* Wk    = (const float*)d_in[5];
    const float* bk    = (const float*)d_in[6];
    const float* Wv    = (const float*)d_in[7];
    const float* bv    = (const float*)d_in[8];
    const float* Wo    = (const float*)d_in[9];
    const float* bo    = (const float*)d_in[10];
    float* out = (float*)d_out;

    void *qh, *ql, *kh, *kl, *vh, *vl;
    void *wqh, *wql, *wkh, *wkl, *wvh, *wvl, *woh, *wol;
    void *qph, *kph, *vph, *oh, *ol;
    cudaGetSymbolAddress(&qh, g_qhi); cudaGetSymbolAddress(&ql, g_qlo);
    cudaGetSymbolAddress(&kh, g_khi); cudaGetSymbolAddress(&kl, g_klo);
    cudaGetSymbolAddress(&vh, g_vhi); cudaGetSymbolAddress(&vl, g_vlo);
    cudaGetSymbolAddress(&wqh, g_WqThi); cudaGetSymbolAddress(&wql, g_WqTlo);
    cudaGetSymbolAddress(&wkh, g_WkThi); cudaGetSymbolAddress(&wkl, g_WkTlo);
    cudaGetSymbolAddress(&wvh, g_WvThi); cudaGetSymbolAddress(&wvl, g_WvTlo);
    cudaGetSymbolAddress(&woh, g_WoThi); cudaGetSymbolAddress(&wol, g_WoTlo);
    cudaGetSymbolAddress(&qph, g_qPhi);
    cudaGetSymbolAddress(&kph, g_kPhi);
    cudaGetSymbolAddress(&vph, g_vPhi);
    cudaGetSymbolAddress(&oh, g_ohi);   cudaGetSymbolAddress(&ol, g_olo);

    cudaFuncSetAttribute((const void*)gemm_mma<128, 128, 0>,
                         cudaFuncAttributeMaxDynamicSharedMemorySize, GEMM128_SMEM);
    cudaFuncSetAttribute((const void*)gemm_proj_all,
                         cudaFuncAttributeMaxDynamicSharedMemorySize, GEMM128_SMEM);
    cudaFuncSetAttribute((const void*)mqa_attn_mma,
                         cudaFuncAttributeMaxDynamicSharedMemorySize, ATTN_SMEM);

    // --- prep ---
    {
        dim3 blk(32, 8);
        TW2 tqo;
        tqo.W[0] = Wq; tqo.Thi[0] = (bf16*)wqh; tqo.Tlo[0] = (bf16*)wql;
        tqo.W[1] = Wo; tqo.Thi[1] = (bf16*)woh; tqo.Tlo[1] = (bf16*)wol;
        transpose_split_w2<<<dim3(HID_DIM / 32, KDIM / 32, 2), blk>>>(tqo, KDIM, HID_DIM);
        TW2 tkv;
        tkv.W[0] = Wk; tkv.Thi[0] = (bf16*)wkh; tkv.Tlo[0] = (bf16*)wkl;
        tkv.W[1] = Wv; tkv.Thi[1] = (bf16*)wvh; tkv.Tlo[1] = (bf16*)wvl;
        transpose_split_w2<<<dim3(HDIM / 32, KDIM / 32, 2), blk>>>(tkv, KDIM, HDIM);

        const int n8 = MROWS * KDIM / 8;
        SR3 sr;
        sr.X[0] = (const float4*)query; sr.hi[0] = (uint4*)qh; sr.lo[0] = (uint4*)ql;
        sr.X[1] = (const float4*)key;   sr.hi[1] = (uint4*)kh; sr.lo[1] = (uint4*)kl;
        sr.X[2] = (const float4*)value; sr.hi[2] = (uint4*)vh; sr.lo[2] = (uint4*)vl;
        split_rows3<<<dim3((n8 + 255) / 256, 3), 256>>>(sr, n8);
    }
    // --- merged Q/K/V projections (fp16 hi-only epilogues; Q scaled 1/32) ---
    {
        ProjArgs a;
        a.qAhi = (const bf16*)qh; a.qAlo = (const bf16*)ql;
        a.qBhi = (const bf16*)wqh; a.qBlo = (const bf16*)wql;
        a.qb = bq; a.qC = (__half*)qph;
        a.kvAhi[0] = (const bf16*)kh; a.kvAlo[0] = (const bf16*)kl;
        a.kvBhi[0] = (const bf16*)wkh; a.kvBlo[0] = (const bf16*)wkl;
        a.kvb[0] = bk; a.kvC[0] = (__half*)kph;
        a.kvAhi[1] = (const bf16*)vh; a.kvAlo[1] = (const bf16*)vl;
        a.kvBhi[1] = (const bf16*)wvh; a.kvBlo[1] = (const bf16*)wvl;
        a.kvb[1] = bv; a.kvC[1] = (__half*)vph;
        gemm_proj_all<<<dim3(HID_DIM / 128, MROWS / 128, 3), 256, GEMM128_SMEM>>>(a);
    }

    // --- tensor-core attention (pure fp16) ---
    {
        dim3 grid(SEQ / 128, NHEAD, BATCH);
        mqa_attn_mma<<<grid, 256, ATTN_SMEM>>>(
            (const __half*)qph, (const __half*)kph, (const __half*)vph,
            (bf16*)oh, (bf16*)ol);
    }

    // --- O-projection -> d_out (fp32 + bias) ---
    gemm_mma<128, 128, 0><<<dim3(IN_DIM / 128, MROWS / 128), 256, GEMM128_SMEM>>>(
        (const bf16*)oh, (const bf16*)ol, (const bf16*)woh, (const bf16*)wol,
        bo, out, nullptr, 1.0f, IN_DIM);
}

// round 14
// speedup vs baseline: 1.1315x; 1.1315x over previous
#include <cuda_runtime.h>
#include <cuda_bf16.h>
#include <cuda_fp16.h>
#include <cstdint>

typedef __nv_bfloat16 bf16;

#define BATCH 2
#define SEQ 2048
#define IN_DIM 1024
#define HID_DIM 1024
#define NHEAD 16
#define HDIM 64
#define KDIM 1024
#define MROWS 4096

// ---------------------------------------------------------------------------
// Scratch (__device__ globals; allocation-free rule)
// ---------------------------------------------------------------------------
__device__ bf16 g_qhi[MROWS * KDIM], g_qlo[MROWS * KDIM];
__device__ bf16 g_khi[MROWS * KDIM], g_klo[MROWS * KDIM];
__device__ bf16 g_vhi[MROWS * KDIM], g_vlo[MROWS * KDIM];
__device__ bf16 g_WqThi[HID_DIM * KDIM], g_WqTlo[HID_DIM * KDIM];
__device__ bf16 g_WkThi[HDIM * KDIM],   g_WkTlo[HDIM * KDIM];
__device__ bf16 g_WvThi[HDIM * KDIM],   g_WvTlo[HDIM * KDIM];
__device__ __half g_WoTh[IN_DIM * KDIM];          // fp16 single for 2-term O-proj
// projected fp16 operands for attention (all single fp16): Q scaled by 1/32
__device__ __half g_qPhi[MROWS * HID_DIM];
__device__ __half g_kPhi[MROWS * HDIM];
__device__ __half g_vPhi[MROWS * HDIM];
// attention output, fp16 exact split (A operand of 2-term O-projection)
__device__ __half g_ohi[MROWS * HID_DIM], g_olo[MROWS * HID_DIM];

// ---------------------------------------------------------------------------
// PTX helpers (all sm_80-era; legal in family-generic PTX)
// ---------------------------------------------------------------------------
__device__ __forceinline__ uint32_t smem_u32(const void* p) {
    uint32_t a;
    asm("{ .reg .u64 t; cvta.to.shared.u64 t, %1; cvt.u32.u64 %0, t; }"
        : "=r"(a) : "l"(p));
    return a;
}
__device__ __forceinline__ void ldsm_x4(uint32_t* r, uint32_t addr) {
    asm volatile("ldmatrix.sync.aligned.m8n8.x4.shared.b16 {%0,%1,%2,%3}, [%4];"
                 : "=r"(r[0]), "=r"(r[1]), "=r"(r[2]), "=r"(r[3]) : "r"(addr));
}
__device__ __forceinline__ void ldsm_x4_t(uint32_t* r, uint32_t addr) {
    asm volatile("ldmatrix.sync.aligned.m8n8.x4.trans.shared.b16 {%0,%1,%2,%3}, [%4];"
                 : "=r"(r[0]), "=r"(r[1]), "=r"(r[2]), "=r"(r[3]) : "r"(addr));
}
__device__ __forceinline__ void mma_bf16(float* d, const uint32_t* a,
                                         const uint32_t* b) {
    asm volatile(
        "mma.sync.aligned.m16n8k16.row.col.f32.bf16.bf16.f32 "
        "{%0,%1,%2,%3}, {%4,%5,%6,%7}, {%8,%9}, {%0,%1,%2,%3};"
        : "+f"(d[0]), "+f"(d[1]), "+f"(d[2]), "+f"(d[3])
        : "r"(a[0]), "r"(a[1]), "r"(a[2]), "r"(a[3]), "r"(b[0]), "r"(b[1]));
}
__device__ __forceinline__ void mma_f16(float* d, const uint32_t* a,
                                        const uint32_t* b) {
    asm volatile(
        "mma.sync.aligned.m16n8k16.row.col.f32.f16.f16.f32 "
        "{%0,%1,%2,%3}, {%4,%5,%6,%7}, {%8,%9}, {%0,%1,%2,%3};"
        : "+f"(d[0]), "+f"(d[1]), "+f"(d[2]), "+f"(d[3])
        : "r"(a[0]), "r"(a[1]), "r"(a[2]), "r"(a[3]), "r"(b[0]), "r"(b[1]));
}
__device__ __forceinline__ void cp16(uint32_t smem, const void* g) {
    asm volatile("cp.async.cg.shared.global [%0], [%1], 16;"
                 :: "r"(smem), "l"(g));
}
__device__ __forceinline__ void cp_commit() {
    asm volatile("cp.async.commit_group;" ::: "memory");
}
__device__ __forceinline__ void cp_wait1() {
    asm volatile("cp.async.wait_group 1;" ::: "memory");
}
__device__ __forceinline__ void cp_wait0() {
    asm volatile("cp.async.wait_group 0;" ::: "memory");
}
__device__ __forceinline__ void split_pack_h(float e, float o,
                                             uint32_t& hp, uint32_t& lp) {
    const __half he = __float2half_rn(e), ho = __float2half_rn(o);
    const __half le = __float2half_rn(e - __half2float(he));
    const __half lo2 = __float2half_rn(o - __half2float(ho));
    __half2 H(he, ho), L(le, lo2);
    hp = *reinterpret_cast<uint32_t*>(&H);
    lp = *reinterpret_cast<uint32_t*>(&L);
}
__device__ __forceinline__ uint32_t pack_h2(float e, float o) {
    __half2 P(__float2half_rn(e), __float2half_rn(o));
    return *reinterpret_cast<uint32_t*>(&P);
}
__device__ __forceinline__ uint32_t pack_b2(float e, float o) {
    __nv_bfloat162 P(__float2bfloat16(e), __float2bfloat16(o));
    return *reinterpret_cast<uint32_t*>(&P);
}

// ---------------------------------------------------------------------------
// Prep kernels
// ---------------------------------------------------------------------------
// z=0: bf16 hi/lo split transpose (Wq). z=1: fp16 single transpose (Wo).
struct TQO {
    const float *Wq, *Wo;
    bf16 *qThi, *qTlo;
    __half* oTh;
};
__global__ void transpose_qo(TQO a, int K, int N)
{
    __shared__ float t[32][33];
    const int n0 = blockIdx.x * 32, k0 = blockIdx.y * 32;
    const int tx = threadIdx.x, ty = threadIdx.y;
    const float* W = (blockIdx.z == 0) ? a.Wq : a.Wo;
#pragma unroll
    for (int i = 0; i < 32; i += 8)
        t[ty + i][tx] = W[(size_t)(k0 + ty + i) * N + n0 + tx];
    __syncthreads();
#pragma unroll
    for (int i = 0; i < 32; i += 8) {
        const float v = t[tx][ty + i];
        const size_t idx = (size_t)(n0 + ty + i) * K + k0 + tx;
        if (blockIdx.z == 0) {
            const bf16 h = __float2bfloat16(v);
            a.qThi[idx] = h;
            a.qTlo[idx] = __float2bfloat16(v - __bfloat162float(h));
        } else {
            a.oTh[idx] = __float2half_rn(v);
        }
    }
}
struct TW2 { const float* W[2]; bf16* Thi[2]; bf16* Tlo[2]; };
__global__ void transpose_split_w2(TW2 a, int K, int N)
{
    __shared__ float t[32][33];
    const int z = blockIdx.z;
    const int n0 = blockIdx.x * 32, k0 = blockIdx.y * 32;
    const int tx = threadIdx.x, ty = threadIdx.y;
#pragma unroll
    for (int i = 0; i < 32; i += 8)
        t[ty + i][tx] = a.W[z][(size_t)(k0 + ty + i) * N + n0 + tx];
    __syncthreads();
#pragma unroll
    for (int i = 0; i < 32; i += 8) {
        const float v = t[tx][ty + i];
        const bf16 h = __float2bfloat16(v);
        const size_t idx = (size_t)(n0 + ty + i) * K + k0 + tx;
        a.Thi[z][idx] = h;
        a.Tlo[z][idx] = __float2bfloat16(v - __bfloat162float(h));
    }
}

// vectorized hi/lo split: 8 fp32 in (2x float4), uint4 hi + uint4 lo out
struct SR3 { const float4* X[3]; uint4* hi[3]; uint4* lo[3]; };
__global__ void split_rows3(SR3 a, int n8)
{
    const int z = blockIdx.y;
    const int i = blockIdx.x * blockDim.x + threadIdx.x;
    if (i < n8) {
        const float4 v0 = a.X[z][2 * i];
        const float4 v1 = a.X[z][2 * i + 1];
        const bf16 h0 = __float2bfloat16(v0.x), h1 = __float2bfloat16(v0.y);
        const bf16 h2 = __float2bfloat16(v0.z), h3 = __float2bfloat16(v0.w);
        const bf16 h4 = __float2bfloat16(v1.x), h5 = __float2bfloat16(v1.y);
        const bf16 h6 = __float2bfloat16(v1.z), h7 = __float2bfloat16(v1.w);
        uint4 H, L;
        H.x = pack_b2(v0.x, v0.y);
        H.y = pack_b2(v0.z, v0.w);
        H.z = pack_b2(v1.x, v1.y);
        H.w = pack_b2(v1.z, v1.w);
        L.x = pack_b2(v0.x - __bfloat162float(h0), v0.y - __bfloat162float(h1));
        L.y = pack_b2(v0.z - __bfloat162float(h2), v0.w - __bfloat162float(h3));
        L.z = pack_b2(v1.x - __bfloat162float(h4), v1.y - __bfloat162float(h5));
        L.w = pack_b2(v1.z - __bfloat162float(h6), v1.w - __bfloat162float(h7));
        a.hi[z][i] = H;
        a.lo[z][i] = L;
    }
}

// ---------------------------------------------------------------------------
// cp.async double-buffered mma.sync bf16 3-term split GEMM core (K-chunk 64).
// EPI=2: fp16 hi-only Chi=(acc+bias)*scale.
// ---------------------------------------------------------------------------
template <int BM, int BN>
__device__ __forceinline__ void gemm_core(
    const bf16* Ahi, const bf16* Alo, const bf16* Bhi, const bf16* Blo,
    const float* bias, __half* Chi,
    float scale, int Ntot, int m0, int n0, char* smem)
{
    constexpr int MF = BM / 64;
    constexpr int WN = BN / 2;
    constexpr int NF = WN / 8;
    constexpr uint32_t ROWB = 144;
    constexpr uint32_t OAL = BM * ROWB;
    constexpr uint32_t OBH = 2 * BM * ROWB;
    constexpr uint32_t OBL = OBH + BN * ROWB;
    constexpr uint32_t STAGE = (2 * BM + 2 * BN) * ROWB;
    constexpr int NCH = KDIM / 64;

    const uint32_t uS = smem_u32(smem);
    const int tid = threadIdx.x;
    const int wid = tid >> 5, lane = tid & 31;
    const int warp_m = wid & 3, warp_n = wid >> 2;
    const int lrow = lane & 15;
    const int lcol = (lane >> 4) * 8;

    const bf16* a_hi = Ahi + (size_t)m0 * KDIM;
    const bf16* a_lo = Alo + (size_t)m0 * KDIM;
    const bf16* b_hi = Bhi + (size_t)n0 * KDIM;
    const bf16* b_lo = Blo + (size_t)n0 * KDIM;

    auto issue = [&](int ch, int buf) {
        const int k0 = ch * 64;
        const uint32_t base = uS + (uint32_t)buf * STAGE;
#pragma unroll
        for (int i = tid; i < BM * 8; i += 256) {
            const int r = i >> 3, c8 = (i & 7) * 8;
            const uint32_t so = (uint32_t)r * ROWB + c8 * 2;
            const size_t g = (size_t)r * KDIM + k0 + c8;
            cp16(base + so, a_hi + g);
            cp16(base + OAL + so, a_lo + g);
        }
#pragma unroll
        for (int i = tid; i < BN * 8; i += 256) {
            const int r = i >> 3, c8 = (i & 7) * 8;
            const uint32_t so = (uint32_t)r * ROWB + c8 * 2;
            const size_t g = (size_t)r * KDIM + k0 + c8;
            cp16(base + OBH + so, b_hi + g);
            cp16(base + OBL + so, b_lo + g);
        }
    };

    float acc[MF][NF][4] = {};

    issue(0, 0);
    cp_commit();

    for (int ch = 0; ch < NCH; ch++) {
        if (ch + 1 < NCH) {
            issue(ch + 1, (ch + 1) & 1);
            cp_commit();
            cp_wait1();
        } else {
            cp_wait0();
        }
        __syncthreads();

        const uint32_t base = uS + (uint32_t)(ch & 1) * STAGE;
#pragma unroll
        for (int ks = 0; ks < 4; ks++) {
            const int kk = ks * 16 + lcol;
            uint32_t ah[MF][4], al[MF][4];
#pragma unroll
            for (int mf = 0; mf < MF; mf++) {
                const int row = warp_m * (BM / 4) + mf * 16 + lrow;
                const uint32_t off = (uint32_t)row * ROWB + kk * 2;
                ldsm_x4(ah[mf], base + off);
                ldsm_x4(al[mf], base + OAL + off);
            }
            uint32_t bh[NF][2], bl[NF][2];
#pragma unroll
            for (int p = 0; p < NF / 2; p++) {
                const int row = warp_n * WN + p * 16 + lrow;
                const uint32_t off = (uint32_t)row * ROWB + kk * 2;
                uint32_t r4[4];
                ldsm_x4(r4, base + OBH + off);
                bh[2 * p][0] = r4[0]; bh[2 * p][1] = r4[2];
                bh[2 * p + 1][0] = r4[1]; bh[2 * p + 1][1] = r4[3];
                ldsm_x4(r4, base + OBL + off);
                bl[2 * p][0] = r4[0]; bl[2 * p][1] = r4[2];
                bl[2 * p + 1][0] = r4[1]; bl[2 * p + 1][1] = r4[3];
            }
#pragma unroll
            for (int mf = 0; mf < MF; mf++)
#pragma unroll
                for (int nf = 0; nf < NF; nf++) {
                    mma_bf16(acc[mf][nf], ah[mf], bh[nf]);
                    mma_bf16(acc[mf][nf], ah[mf], bl[nf]);
                    mma_bf16(acc[mf][nf], al[mf], bh[nf]);
                }
        }
        __syncthreads();
    }

    const int gid = lane >> 2, t4 = lane & 3;
#pragma unroll
    for (int mf = 0; mf < MF; mf++) {
        const int row = m0 + warp_m * (BM / 4) + mf * 16 + gid;
#pragma unroll
        for (int nf = 0; nf < NF; nf++) {
            const int col = n0 + warp_n * WN + nf * 8 + t4 * 2;
            const float b0 = bias[col], b1 = bias[col + 1];
            *(uint32_t*)(Chi + (size_t)row * Ntot + col) =
                pack_h2((acc[mf][nf][0] + b0) * scale,
                        (acc[mf][nf][1] + b1) * scale);
            *(uint32_t*)(Chi + (size_t)(row + 8) * Ntot + col) =
                pack_h2((acc[mf][nf][2] + b0) * scale,
                        (acc[mf][nf][3] + b1) * scale);
        }
    }
}

// ---------------------------------------------------------------------------
// Merged Q/K/V projection launch. grid (8, 32, 3):
//   z=0: Q-proj 128x128 tiles; z=1/2: K/V-proj 64x64 tiles (64 CTAs active)
// ---------------------------------------------------------------------------
struct ProjArgs {
    const bf16 *qAhi, *qAlo, *qBhi, *qBlo; const float* qb; __half* qC;
    const bf16 *kvAhi[2], *kvAlo[2], *kvBhi[2], *kvBlo[2];
    const float* kvb[2]; __half* kvC[2];
};
__global__ __launch_bounds__(256) void gemm_proj_all(ProjArgs a)
{
    extern __shared__ char smem[];
    const int z = blockIdx.z;
    if (z == 0) {
        gemm_core<128, 128>(a.qAhi, a.qAlo, a.qBhi, a.qBlo, a.qb,
                            a.qC, 1.0f / 32.0f, HID_DIM,
                            blockIdx.y * 128, blockIdx.x * 128, smem);
    } else {
        const int id = blockIdx.y * 8 + blockIdx.x;   // 0..255
        if (id >= MROWS / 64) return;                 // 64 active
        const int s = z - 1;
        gemm_core<64, 64>(a.kvAhi[s], a.kvAlo[s], a.kvBhi[s], a.kvBlo[s],
                          a.kvb[s], a.kvC[s], 1.0f, HDIM,
                          id * 64, 0, smem);
    }
}

// ---------------------------------------------------------------------------
// O-projection: 2-term fp16 GEMM.  out[M,N] = (Ah+Al)[M,K] @ Bh[N,K]^T + bias
// A = attention output exact fp16 split; Bh = fp16(Wo^T). fp32 epilogue.
// ---------------------------------------------------------------------------
__global__ __launch_bounds__(256) void gemm_o(
    const __half* __restrict__ Ahi, const __half* __restrict__ Alo,
    const __half* __restrict__ Bh,
    const float* __restrict__ bias, float* __restrict__ C)
{
    constexpr int BM = 128, BN = 128;
    constexpr int MF = 2, WN = 64, NF = 8;
    constexpr uint32_t ROWB = 144;
    constexpr uint32_t OAL = BM * ROWB;
    constexpr uint32_t OBH = 2 * BM * ROWB;
    constexpr uint32_t STAGE = (2 * BM + BN) * ROWB;   // 55296
    constexpr int NCH = KDIM / 64;

    extern __shared__ char smem[];
    const uint32_t uS = smem_u32(smem);
    const int tid = threadIdx.x;
    const int wid = tid >> 5, lane = tid & 31;
    const int warp_m = wid & 3, warp_n = wid >> 2;
    const int m0 = blockIdx.y * BM;
    const int n0 = blockIdx.x * BN;
    const int lrow = lane & 15;
    const int lcol = (lane >> 4) * 8;

    const __half* a_hi = Ahi + (size_t)m0 * KDIM;
    const __half* a_lo = Alo + (size_t)m0 * KDIM;
    const __half* b_h = Bh + (size_t)n0 * KDIM;

    auto issue = [&](int ch, int buf) {
        const int k0 = ch * 64;
        const uint32_t base = uS + (uint32_t)buf * STAGE;
#pragma unroll
        for (int i = tid; i < BM * 8; i += 256) {
            const int r = i >> 3, c8 = (i & 7) * 8;
            const uint32_t so = (uint32_t)r * ROWB + c8 * 2;
            const size_t g = (size_t)r * KDIM + k0 + c8;
            cp16(base + so, a_hi + g);
            cp16(base + OAL + so, a_lo + g);
        }
#pragma unroll
        for (int i = tid; i < BN * 8; i += 256) {
            const int r = i >> 3, c8 = (i & 7) * 8;
            const uint32_t so = (uint32_t)r * ROWB + c8 * 2;
            cp16(base + OBH + so, b_h + (size_t)r * KDIM + k0 + c8);
        }
    };

    float acc[MF][NF][4] = {};

    issue(0, 0);
    cp_commit();

    for (int ch = 0; ch < NCH; ch++) {
        if (ch + 1 < NCH) {
            issue(ch + 1, (ch + 1) & 1);
            cp_commit();
            cp_wait1();
        } else {
            cp_wait0();
        }
        __syncthreads();

        const uint32_t base = uS + (uint32_t)(ch & 1) * STAGE;
#pragma unroll
        for (int ks = 0; ks < 4; ks++) {
            const int kk = ks * 16 + lcol;
            uint32_t ah[MF][4], al[MF][4];
#pragma unroll
            for (int mf = 0; mf < MF; mf++) {
                const int row = warp_m * 32 + mf * 16 + lrow;
                const uint32_t off = (uint32_t)row * ROWB + kk * 2;
                ldsm_x4(ah[mf], base + off);
                ldsm_x4(al[mf], base + OAL + off);
            }
            uint32_t bh[NF][2];
#pragma unroll
            for (int p = 0; p < NF / 2; p++) {
                const int row = warp_n * WN + p * 16 + lrow;
                const uint32_t off = (uint32_t)row * ROWB + kk * 2;
                uint32_t r4[4];
                ldsm_x4(r4, base + OBH + off);
                bh[2 * p][0] = r4[0]; bh[2 * p][1] = r4[2];
                bh[2 * p + 1][0] = r4[1]; bh[2 * p + 1][1] = r4[3];
            }
#pragma unroll
            for (int mf = 0; mf < MF; mf++)
#pragma unroll
                for (int nf = 0; nf < NF; nf++) {
                    mma_f16(acc[mf][nf], ah[mf], bh[nf]);
                    mma_f16(acc[mf][nf], al[mf], bh[nf]);
                }
        }
        __syncthreads();
    }

    const int gid = lane >> 2, t4 = lane & 3;
#pragma unroll
    for (int mf = 0; mf < MF; mf++) {
        const int row = m0 + warp_m * 32 + mf * 16 + gid;
#pragma unroll
        for (int nf = 0; nf < NF; nf++) {
            const int col = n0 + warp_n * WN + nf * 8 + t4 * 2;
            const float b0 = bias[col], b1 = bias[col + 1];
            float2 o0 = make_float2(acc[mf][nf][0] + b0, acc[mf][nf][1] + b1);
            float2 o1 = make_float2(acc[mf][nf][2] + b0, acc[mf][nf][3] + b1);
            *(float2*)(C + (size_t)row * IN_DIM + col) = o0;
            *(float2*)(C + (size_t)(row + 8) * IN_DIM + col) = o1;
        }
    }
}

// ---------------------------------------------------------------------------
// Tensor-core MQA attention, pure single-fp16:
//   scores = Q·K (1 term);  PV = P·V (1 term)
// Epilogue: exact fp16 hi/lo split of normalized output.
// ---------------------------------------------------------------------------
__global__ __launch_bounds__(256) void mqa_attn_mma(
    const __half* __restrict__ Qhi,
    const __half* __restrict__ Khi, const __half* __restrict__ Vhi,
    __half* __restrict__ Ohi, __half* __restrict__ Olo)
{
    constexpr uint32_t ROWB = 144;
    constexpr uint32_t ST0 = 128 * ROWB;
    constexpr uint32_t STG = 128 * ROWB;
    constexpr uint32_t VHI = 64 * ROWB;
    constexpr int NCH = SEQ / 64;

    extern __shared__ char smc[];
    const uint32_t uS = smem_u32(smc);

    const int tid = threadIdx.x, wid = tid >> 5, lane = tid & 31;
    const int h = blockIdx.y, b = blockIdx.z;
    const int q0 = blockIdx.x * 128;
    const size_t qrow0 = (size_t)b * SEQ + q0;
    const int lrow = lane & 15;
    const int lcol = (lane >> 4) * 8;

    const __half* kh_g = Khi + (size_t)b * SEQ * HDIM;
    const __half* vh_g = Vhi + (size_t)b * SEQ * HDIM;

    auto issue = [&](int ch, int buf) {
        const int k0 = ch * 64;
        const uint32_t base = uS + ST0 + (uint32_t)buf * STG;
#pragma unroll
        for (int i = tid; i < 64 * 8; i += 256) {
            const int r = i >> 3, c8 = (i & 7) * 8;
            const uint32_t so = (uint32_t)r * ROWB + c8 * 2;
            const size_t g = (size_t)(k0 + r) * HDIM + c8;
            cp16(base + so, kh_g + g);
            cp16(base + VHI + so, vh_g + g);
        }
    };

    issue(0, 0);
    cp_commit();
    {
        const __half* qh_g = Qhi + qrow0 * HID_DIM + h * HDIM;
#pragma unroll
        for (int i = tid; i < 128 * 8; i += 256) {
            const int r = i >> 3, c8 = (i & 7) * 8;
            const uint32_t so = (uint32_t)r * ROWB + c8 * 2;
            *(uint4*)(smc + so) = *(const uint4*)(qh_g + (size_t)r * HID_DIM + c8);
        }
    }
    __syncthreads();
    uint32_t qh[4][4];
#pragma unroll
    for (int ks = 0; ks < 4; ks++) {
        const uint32_t off = (uint32_t)(wid * 16 + lrow) * ROWB + (ks * 16 + lcol) * 2;
        ldsm_x4(qh[ks], uS + off);
    }

    float m1 = -1e30f, m2 = -1e30f, lp1 = 0.0f, lp2 = 0.0f;
    float oacc[8][4] = {};

    for (int ch = 0; ch < NCH; ch++) {
        if (ch + 1 < NCH) {
            issue(ch + 1, (ch + 1) & 1);
            cp_commit();
            cp_wait1();
        } else {
            cp_wait0();
        }
        __syncthreads();

        const uint32_t base = uS + ST0 + (uint32_t)(ch & 1) * STG;

        float sc[8][4] = {};
#pragma unroll
        for (int ks = 0; ks < 4; ks++) {
#pragma unroll
            for (int p = 0; p < 4; p++) {
                const uint32_t off =
                    (uint32_t)(p * 16 + lrow) * ROWB + (ks * 16 + lcol) * 2;
                uint32_t rh[4];
                ldsm_x4(rh, base + off);
                uint32_t b0[2] = {rh[0], rh[2]}, b1[2] = {rh[1], rh[3]};
                mma_f16(sc[2 * p], qh[ks], b0);
                mma_f16(sc[2 * p + 1], qh[ks], b1);
            }
        }

        float mx1 = m1, mx2 = m2;
#pragma unroll
        for (int nf = 0; nf < 8; nf++) {
            mx1 = fmaxf(mx1, fmaxf(sc[nf][0], sc[nf][1]));
            mx2 = fmaxf(mx2, fmaxf(sc[nf][2], sc[nf][3]));
        }
        mx1 = fmaxf(mx1, __shfl_xor_sync(0xffffffffu, mx1, 1));
        mx1 = fmaxf(mx1, __shfl_xor_sync(0xffffffffu, mx1, 2));
        mx2 = fmaxf(mx2, __shfl_xor_sync(0xffffffffu, mx2, 1));
        mx2 = fmaxf(mx2, __shfl_xor_sync(0xffffffffu, mx2, 2));
        const float a1 = __expf(m1 - mx1);
        const float a2 = __expf(m2 - mx2);
        m1 = mx1; m2 = mx2;

        float s1 = 0.0f, s2 = 0.0f;
        uint32_t pr1[8], pr2[8];
#pragma unroll
        for (int nf = 0; nf < 8; nf++) {
            const float p0 = __expf(sc[nf][0] - mx1);
            const float p1 = __expf(sc[nf][1] - mx1);
            const float p2 = __expf(sc[nf][2] - mx2);
            const float p3 = __expf(sc[nf][3] - mx2);
            s1 += p0 + p1; s2 += p2 + p3;
            pr1[nf] = pack_h2(p0, p1);
            pr2[nf] = pack_h2(p2, p3);
        }
        lp1 = lp1 * a1 + s1;
        lp2 = lp2 * a2 + s2;
#pragma unroll
        for (int nf = 0; nf < 8; nf++) {
            oacc[nf][0] *= a1; oacc[nf][1] *= a1;
            oacc[nf][2] *= a2; oacc[nf][3] *= a2;
        }

#pragma unroll
        for (int ks = 0; ks < 4; ks++) {
            uint32_t pa[4] = {pr1[2 * ks], pr2[2 * ks],
                              pr1[2 * ks + 1], pr2[2 * ks + 1]};
#pragma unroll
            for (int p = 0; p < 4; p++) {
                const uint32_t off =
                    (uint32_t)(ks * 16 + lrow) * ROWB + (p * 16 + lcol) * 2;
                uint32_t rh[4];
                ldsm_x4_t(rh, base + VHI + off);
                uint32_t b0[2] = {rh[0], rh[1]}, b1[2] = {rh[2], rh[3]};
                mma_f16(oacc[2 * p], pa, b0);
                mma_f16(oacc[2 * p + 1], pa, b1);
            }
        }
        __syncthreads();
    }

    lp1 += __shfl_xor_sync(0xffffffffu, lp1, 1);
    lp1 += __shfl_xor_sync(0xffffffffu, lp1, 2);
    lp2 += __shfl_xor_sync(0xffffffffu, lp2, 1);
    lp2 += __shfl_xor_sync(0xffffffffu, lp2, 2);
    const float i1 = 1.0f / lp1, i2 = 1.0f / lp2;

    const size_t row1 = qrow0 + wid * 16 + (lane >> 2);
    const size_t row2 = row1 + 8;
#pragma unroll
    for (int nf = 0; nf < 8; nf++) {
        const int col = h * HDIM + nf * 8 + (lane & 3) * 2;
        uint32_t hp, lp;
        split_pack_h(oacc[nf][0] * i1, oacc[nf][1] * i1, hp, lp);
        *(uint32_t*)(Ohi + row1 * HID_DIM + col) = hp;
        *(uint32_t*)(Olo + row1 * HID_DIM + col) = lp;
        split_pack_h(oacc[nf][2] * i2, oacc[nf][3] * i2, hp, lp);
        *(uint32_t*)(Ohi + row2 * HID_DIM + col) = hp;
        *(uint32_t*)(Olo + row2 * HID_DIM + col) = lp;
    }
}

static const int GEMM128_SMEM = 2 * (2 * 128 + 2 * 128) * 144;  // 147456
static const int GEMMO_SMEM   = 2 * (2 * 128 + 128) * 144;      // 110592
static const int ATTN_SMEM    = 128 * 144 + 2 * 128 * 144;      // 55296

// ---------------------------------------------------------------------------
// Launch
// ---------------------------------------------------------------------------
extern "C" void kernel_launch(void* const* d_in, const int* in_sizes, int n_in,
                              void* d_out, int out_size)
{
    const float* query = (const float*)d_in[0];
    const float* key   = (const float*)d_in[1];
    const float* value = (const float*)d_in[2];
    const float* Wq    = (const float*)d_in[3];
    const float* bq    = (const float*)d_in[4];
    const float* Wk    = (const float*)d_in[5];
    const float* bk    = (const float*)d_in[6];
    const float* Wv    = (const float*)d_in[7];
    const float* bv    = (const float*)d_in[8];
    const float* Wo    = (const float*)d_in[9];
    const float* bo    = (const float*)d_in[10];
    float* out = (float*)d_out;

    void *qh, *ql, *kh, *kl, *vh, *vl;
    void *wqh, *wql, *wkh, *wkl, *wvh, *wvl, *woh;
    void *qph, *kph, *vph, *oh, *ol;
    cudaGetSymbolAddress(&qh, g_qhi); cudaGetSymbolAddress(&ql, g_qlo);
    cudaGetSymbolAddress(&kh, g_khi); cudaGetSymbolAddress(&kl, g_klo);
    cudaGetSymbolAddress(&vh, g_vhi); cudaGetSymbolAddress(&vl, g_vlo);
    cudaGetSymbolAddress(&wqh, g_WqThi); cudaGetSymbolAddress(&wql, g_WqTlo);
    cudaGetSymbolAddress(&wkh, g_WkThi); cudaGetSymbolAddress(&wkl, g_WkTlo);
    cudaGetSymbolAddress(&wvh, g_WvThi); cudaGetSymbolAddress(&wvl, g_WvTlo);
    cudaGetSymbolAddress(&woh, g_WoTh);
    cudaGetSymbolAddress(&qph, g_qPhi);
    cudaGetSymbolAddress(&kph, g_kPhi);
    cudaGetSymbolAddress(&vph, g_vPhi);
    cudaGetSymbolAddress(&oh, g_ohi);   cudaGetSymbolAddress(&ol, g_olo);

    cudaFuncSetAttribute((const void*)gemm_proj_all,
                         cudaFuncAttributeMaxDynamicSharedMemorySize, GEMM128_SMEM);
    cudaFuncSetAttribute((const void*)gemm_o,
                         cudaFuncAttributeMaxDynamicSharedMemorySize, GEMMO_SMEM);
    cudaFuncSetAttribute((const void*)mqa_attn_mma,
                         cudaFuncAttributeMaxDynamicSharedMemorySize, ATTN_SMEM);

    // --- prep ---
    {
        dim3 blk(32, 8);
        TQO tqo;
        tqo.Wq = Wq; tqo.qThi = (bf16*)wqh; tqo.qTlo = (bf16*)wql;
        tqo.Wo = Wo; tqo.oTh = (__half*)woh;
        transpose_qo<<<dim3(HID_DIM / 32, KDIM / 32, 2), blk>>>(tqo, KDIM, HID_DIM);
        TW2 tkv;
        tkv.W[0] = Wk; tkv.Thi[0] = (bf16*)wkh; tkv.Tlo[0] = (bf16*)wkl;
        tkv.W[1] = Wv; tkv.Thi[1] = (bf16*)wvh; tkv.Tlo[1] = (bf16*)wvl;
        transpose_split_w2<<<dim3(HDIM / 32, KDIM / 32, 2), blk>>>(tkv, KDIM, HDIM);

        const int n8 = MROWS * KDIM / 8;
        SR3 sr;
        sr.X[0] = (const float4*)query; sr.hi[0] = (uint4*)qh; sr.lo[0] = (uint4*)ql;
        sr.X[1] = (const float4*)key;   sr.hi[1] = (uint4*)kh; sr.lo[1] = (uint4*)kl;
        sr.X[2] = (const float4*)value; sr.hi[2] = (uint4*)vh; sr.lo[2] = (uint4*)vl;
        split_rows3<<<dim3((n8 + 255) / 256, 3), 256>>>(sr, n8);
    }
    // --- merged Q/K/V projections (fp16 hi-only epilogues; Q scaled 1/32) ---
    {
        ProjArgs a;
        a.qAhi = (const bf16*)qh; a.qAlo = (const bf16*)ql;
        a.qBhi = (const bf16*)wqh; a.qBlo = (const bf16*)wql;
        a.qb = bq; a.qC = (__half*)qph;
        a.kvAhi[0] = (const bf16*)kh; a.kvAlo[0] = (const bf16*)kl;
        a.kvBhi[0] = (const bf16*)wkh; a.kvBlo[0] = (const bf16*)wkl;
        a.kvb[0] = bk; a.kvC[0] = (__half*)kph;
        a.kvAhi[1] = (const bf16*)vh; a.kvAlo[1] = (const bf16*)vl;
        a.kvBhi[1] = (const bf16*)wvh; a.kvBlo[1] = (const bf16*)wvl;
        a.kvb[1] = bv; a.kvC[1] = (__half*)vph;
        gemm_proj_all<<<dim3(HID_DIM / 128, MROWS / 128, 3), 256, GEMM128_SMEM>>>(a);
    }

    // --- tensor-core attention (pure fp16) ---
    {
        dim3 grid(SEQ / 128, NHEAD, BATCH);
        mqa_attn_mma<<<grid, 256, ATTN_SMEM>>>(
            (const __half*)qph, (const __half*)kph, (const __half*)vph,
            (__half*)oh, (__half*)ol);
    }

    // --- O-projection (2-term fp16) -> d_out ---
    gemm_o<<<dim3(IN_DIM / 128, MROWS / 128), 256, GEMMO_SMEM>>>(
        (const __half*)oh, (const __half*)ol, (const __half*)woh, bo, out);
}

// round 15
// speedup vs baseline: 1.2360x; 1.0924x over previous
#include <cuda_runtime.h>
#include <cuda_bf16.h>
#include <cuda_fp16.h>
#include <cstdint>

#define BATCH 2
#define SEQ 2048
#define IN_DIM 1024
#define HID_DIM 1024
#define NHEAD 16
#define HDIM 64
#define KDIM 1024
#define MROWS 4096

// ---------------------------------------------------------------------------
// Scratch (__device__ globals; allocation-free rule)
// ---------------------------------------------------------------------------
// inputs, exact fp16 hi/lo split
__device__ __half g_qhi[MROWS * KDIM], g_qlo[MROWS * KDIM];
__device__ __half g_khi[MROWS * KDIM], g_klo[MROWS * KDIM];
__device__ __half g_vhi[MROWS * KDIM], g_vlo[MROWS * KDIM];
// transposed weights, single fp16 [N][K]
__device__ __half g_WqTh[HID_DIM * KDIM];
__device__ __half g_WkTh[HDIM * KDIM];
__device__ __half g_WvTh[HDIM * KDIM];
__device__ __half g_WoTh[IN_DIM * KDIM];
// projected fp16 operands for attention: Q scaled by 1/32
__device__ __half g_qPhi[MROWS * HID_DIM];
__device__ __half g_kPhi[MROWS * HDIM];
__device__ __half g_vPhi[MROWS * HDIM];
// attention output, exact fp16 split (A operand of 2-term O-projection)
__device__ __half g_ohi[MROWS * HID_DIM], g_olo[MROWS * HID_DIM];

// ---------------------------------------------------------------------------
// PTX helpers (all sm_80-era; legal in family-generic PTX)
// ---------------------------------------------------------------------------
__device__ __forceinline__ uint32_t smem_u32(const void* p) {
    uint32_t a;
    asm("{ .reg .u64 t; cvta.to.shared.u64 t, %1; cvt.u32.u64 %0, t; }"
        : "=r"(a) : "l"(p));
    return a;
}
__device__ __forceinline__ void ldsm_x4(uint32_t* r, uint32_t addr) {
    asm volatile("ldmatrix.sync.aligned.m8n8.x4.shared.b16 {%0,%1,%2,%3}, [%4];"
                 : "=r"(r[0]), "=r"(r[1]), "=r"(r[2]), "=r"(r[3]) : "r"(addr));
}
__device__ __forceinline__ void ldsm_x4_t(uint32_t* r, uint32_t addr) {
    asm volatile("ldmatrix.sync.aligned.m8n8.x4.trans.shared.b16 {%0,%1,%2,%3}, [%4];"
                 : "=r"(r[0]), "=r"(r[1]), "=r"(r[2]), "=r"(r[3]) : "r"(addr));
}
__device__ __forceinline__ void mma_f16(float* d, const uint32_t* a,
                                        const uint32_t* b) {
    asm volatile(
        "mma.sync.aligned.m16n8k16.row.col.f32.f16.f16.f32 "
        "{%0,%1,%2,%3}, {%4,%5,%6,%7}, {%8,%9}, {%0,%1,%2,%3};"
        : "+f"(d[0]), "+f"(d[1]), "+f"(d[2]), "+f"(d[3])
        : "r"(a[0]), "r"(a[1]), "r"(a[2]), "r"(a[3]), "r"(b[0]), "r"(b[1]));
}
__device__ __forceinline__ void cp16(uint32_t smem, const void* g) {
    asm volatile("cp.async.cg.shared.global [%0], [%1], 16;"
                 :: "r"(smem), "l"(g));
}
__device__ __forceinline__ void cp_commit() {
    asm volatile("cp.async.commit_group;" ::: "memory");
}
__device__ __forceinline__ void cp_wait1() {
    asm volatile("cp.async.wait_group 1;" ::: "memory");
}
__device__ __forceinline__ void cp_wait0() {
    asm volatile("cp.async.wait_group 0;" ::: "memory");
}
__device__ __forceinline__ void split_pack_h(float e, float o,
                                             uint32_t& hp, uint32_t& lp) {
    const __half he = __float2half_rn(e), ho = __float2half_rn(o);
    const __half le = __float2half_rn(e - __half2float(he));
    const __half lo2 = __float2half_rn(o - __half2float(ho));
    __half2 H(he, ho), L(le, lo2);
    hp = *reinterpret_cast<uint32_t*>(&H);
    lp = *reinterpret_cast<uint32_t*>(&L);
}
__device__ __forceinline__ uint32_t pack_h2(float e, float o) {
    __half2 P(__float2half_rn(e), __float2half_rn(o));
    return *reinterpret_cast<uint32_t*>(&P);
}

// ---------------------------------------------------------------------------
// Prep kernels
// ---------------------------------------------------------------------------
// transpose fp32 W[K,N] -> single fp16 T[N,K]; grid.z picks one of two weights
struct TH2 { const float* W[2]; __half* T[2]; };
__global__ void transpose_h2(TH2 a, int K, int N)
{
    __shared__ float t[32][33];
    const int z = blockIdx.z;
    const int n0 = blockIdx.x * 32, k0 = blockIdx.y * 32;
    const int tx = threadIdx.x, ty = threadIdx.y;
#pragma unroll
    for (int i = 0; i < 32; i += 8)
        t[ty + i][tx] = a.W[z][(size_t)(k0 + ty + i) * N + n0 + tx];
    __syncthreads();
#pragma unroll
    for (int i = 0; i < 32; i += 8)
        a.T[z][(size_t)(n0 + ty + i) * K + k0 + tx] = __float2half_rn(t[tx][ty + i]);
}

// vectorized exact fp16 hi/lo split: 8 fp32 in, uint4 hi + uint4 lo out
struct SR3 { const float4* X[3]; uint4* hi[3]; uint4* lo[3]; };
__global__ void split_rows3(SR3 a, int n8)
{
    const int z = blockIdx.y;
    const int i = blockIdx.x * blockDim.x + threadIdx.x;
    if (i < n8) {
        const float4 v0 = a.X[z][2 * i];
        const float4 v1 = a.X[z][2 * i + 1];
        uint4 H, L;
        split_pack_h(v0.x, v0.y, H.x, L.x);
        split_pack_h(v0.z, v0.w, H.y, L.y);
        split_pack_h(v1.x, v1.y, H.z, L.z);
        split_pack_h(v1.z, v1.w, H.w, L.w);
        a.hi[z][i] = H;
        a.lo[z][i] = L;
    }
}

// ---------------------------------------------------------------------------
// 2-term fp16 GEMM core: C[M,N] = (Ah+Al)[M,K] @ Bh[N,K]^T + bias
// cp.async double-buffered, K-chunk 64.
// EPI=0: fp32 out.  EPI=2: fp16 single out, scaled.
// ---------------------------------------------------------------------------
template <int BM, int BN, int EPI>
__device__ __forceinline__ void gemm_core_h(
    const __half* Ahi, const __half* Alo, const __half* Bh,
    const float* bias, float* C, __half* Chi,
    float scale, int Ntot, int m0, int n0, char* smem)
{
    constexpr int MF = BM / 64;
    constexpr int WN = BN / 2;
    constexpr int NF = WN / 8;
    constexpr uint32_t ROWB = 144;
    constexpr uint32_t OAL = BM * ROWB;
    constexpr uint32_t OBH = 2 * BM * ROWB;
    constexpr uint32_t STAGE = (2 * BM + BN) * ROWB;
    constexpr int NCH = KDIM / 64;

    const uint32_t uS = smem_u32(smem);
    const int tid = threadIdx.x;
    const int wid = tid >> 5, lane = tid & 31;
    const int warp_m = wid & 3, warp_n = wid >> 2;
    const int lrow = lane & 15;
    const int lcol = (lane >> 4) * 8;

    const __half* a_hi = Ahi + (size_t)m0 * KDIM;
    const __half* a_lo = Alo + (size_t)m0 * KDIM;
    const __half* b_h = Bh + (size_t)n0 * KDIM;

    auto issue = [&](int ch, int buf) {
        const int k0 = ch * 64;
        const uint32_t base = uS + (uint32_t)buf * STAGE;
#pragma unroll
        for (int i = tid; i < BM * 8; i += 256) {
            const int r = i >> 3, c8 = (i & 7) * 8;
            const uint32_t so = (uint32_t)r * ROWB + c8 * 2;
            const size_t g = (size_t)r * KDIM + k0 + c8;
            cp16(base + so, a_hi + g);
            cp16(base + OAL + so, a_lo + g);
        }
#pragma unroll
        for (int i = tid; i < BN * 8; i += 256) {
            const int r = i >> 3, c8 = (i & 7) * 8;
            const uint32_t so = (uint32_t)r * ROWB + c8 * 2;
            cp16(base + OBH + so, b_h + (size_t)r * KDIM + k0 + c8);
        }
    };

    float acc[MF][NF][4] = {};

    issue(0, 0);
    cp_commit();

    for (int ch = 0; ch < NCH; ch++) {
        if (ch + 1 < NCH) {
            issue(ch + 1, (ch + 1) & 1);
            cp_commit();
            cp_wait1();
        } else {
            cp_wait0();
        }
        __syncthreads();

        const uint32_t base = uS + (uint32_t)(ch & 1) * STAGE;
#pragma unroll
        for (int ks = 0; ks < 4; ks++) {
            const int kk = ks * 16 + lcol;
            uint32_t ah[MF][4], al[MF][4];
#pragma unroll
            for (int mf = 0; mf < MF; mf++) {
                const int row = warp_m * (BM / 4) + mf * 16 + lrow;
                const uint32_t off = (uint32_t)row * ROWB + kk * 2;
                ldsm_x4(ah[mf], base + off);
                ldsm_x4(al[mf], base + OAL + off);
            }
            uint32_t bh[NF][2];
#pragma unroll
            for (int p = 0; p < NF / 2; p++) {
                const int row = warp_n * WN + p * 16 + lrow;
                const uint32_t off = (uint32_t)row * ROWB + kk * 2;
                uint32_t r4[4];
                ldsm_x4(r4, base + OBH + off);
                bh[2 * p][0] = r4[0]; bh[2 * p][1] = r4[2];
                bh[2 * p + 1][0] = r4[1]; bh[2 * p + 1][1] = r4[3];
            }
#pragma unroll
            for (int mf = 0; mf < MF; mf++)
#pragma unroll
                for (int nf = 0; nf < NF; nf++) {
                    mma_f16(acc[mf][nf], ah[mf], bh[nf]);
                    mma_f16(acc[mf][nf], al[mf], bh[nf]);
                }
        }
        __syncthreads();
    }

    const int gid = lane >> 2, t4 = lane & 3;
#pragma unroll
    for (int mf = 0; mf < MF; mf++) {
        const int row = m0 + warp_m * (BM / 4) + mf * 16 + gid;
#pragma unroll
        for (int nf = 0; nf < NF; nf++) {
            const int col = n0 + warp_n * WN + nf * 8 + t4 * 2;
            const float b0 = bias[col], b1 = bias[col + 1];
            if (EPI == 0) {
                float2 o0 = make_float2(acc[mf][nf][0] + b0, acc[mf][nf][1] + b1);
                float2 o1 = make_float2(acc[mf][nf][2] + b0, acc[mf][nf][3] + b1);
                *(float2*)(C + (size_t)row * Ntot + col) = o0;
                *(float2*)(C + (size_t)(row + 8) * Ntot + col) = o1;
            } else {
                *(uint32_t*)(Chi + (size_t)row * Ntot + col) =
                    pack_h2((acc[mf][nf][0] + b0) * scale,
                            (acc[mf][nf][1] + b1) * scale);
                *(uint32_t*)(Chi + (size_t)(row + 8) * Ntot + col) =
                    pack_h2((acc[mf][nf][2] + b0) * scale,
                            (acc[mf][nf][3] + b1) * scale);
            }
        }
    }
}

// ---------------------------------------------------------------------------
// Merged Q/K/V projection launch. grid (8, 32, 3):
//   z=0: Q-proj 128x128 tiles; z=1/2: K/V-proj 64x64 tiles (64 CTAs active)
// ---------------------------------------------------------------------------
struct ProjArgs {
    const __half *qAhi, *qAlo, *qBh; const float* qb; __half* qC;
    const __half *kvAhi[2], *kvAlo[2], *kvBh[2];
    const float* kvb[2]; __half* kvC[2];
};
__global__ __launch_bounds__(256) void gemm_proj_all(ProjArgs a)
{
    extern __shared__ char smem[];
    const int z = blockIdx.z;
    if (z == 0) {
        gemm_core_h<128, 128, 2>(a.qAhi, a.qAlo, a.qBh, a.qb,
                                 nullptr, a.qC, 1.0f / 32.0f, HID_DIM,
                                 blockIdx.y * 128, blockIdx.x * 128, smem);
    } else {
        const int id = blockIdx.y * 8 + blockIdx.x;   // 0..255
        if (id >= MROWS / 64) return;                 // 64 active
        const int s = z - 1;
        gemm_core_h<64, 64, 2>(a.kvAhi[s], a.kvAlo[s], a.kvBh[s],
                               a.kvb[s], nullptr, a.kvC[s], 1.0f, HDIM,
                               id * 64, 0, smem);
    }
}

// O-projection: 2-term fp16, fp32 epilogue -> d_out
__global__ __launch_bounds__(256) void gemm_o(
    const __half* __restrict__ Ahi, const __half* __restrict__ Alo,
    const __half* __restrict__ Bh,
    const float* __restrict__ bias, float* __restrict__ C)
{
    extern __shared__ char smem[];
    gemm_core_h<128, 128, 0>(Ahi, Alo, Bh, bias, C, nullptr, 1.0f, IN_DIM,
                             blockIdx.y * 128, blockIdx.x * 128, smem);
}

// ---------------------------------------------------------------------------
// Tensor-core MQA attention, pure single-fp16:
//   scores = Q·K (1 term);  PV = P·V (1 term)
// Epilogue: exact fp16 hi/lo split of normalized output.
// ---------------------------------------------------------------------------
__global__ __launch_bounds__(256) void mqa_attn_mma(
    const __half* __restrict__ Qhi,
    const __half* __restrict__ Khi, const __half* __restrict__ Vhi,
    __half* __restrict__ Ohi, __half* __restrict__ Olo)
{
    constexpr uint32_t ROWB = 144;
    constexpr uint32_t ST0 = 128 * ROWB;
    constexpr uint32_t STG = 128 * ROWB;
    constexpr uint32_t VHI = 64 * ROWB;
    constexpr int NCH = SEQ / 64;

    extern __shared__ char smc[];
    const uint32_t uS = smem_u32(smc);

    const int tid = threadIdx.x, wid = tid >> 5, lane = tid & 31;
    const int h = blockIdx.y, b = blockIdx.z;
    const int q0 = blockIdx.x * 128;
    const size_t qrow0 = (size_t)b * SEQ + q0;
    const int lrow = lane & 15;
    const int lcol = (lane >> 4) * 8;

    const __half* kh_g = Khi + (size_t)b * SEQ * HDIM;
    const __half* vh_g = Vhi + (size_t)b * SEQ * HDIM;

    auto issue = [&](int ch, int buf) {
        const int k0 = ch * 64;
        const uint32_t base = uS + ST0 + (uint32_t)buf * STG;
#pragma unroll
        for (int i = tid; i < 64 * 8; i += 256) {
            const int r = i >> 3, c8 = (i & 7) * 8;
            const uint32_t so = (uint32_t)r * ROWB + c8 * 2;
            const size_t g = (size_t)(k0 + r) * HDIM + c8;
            cp16(base + so, kh_g + g);
            cp16(base + VHI + so, vh_g + g);
        }
    };

    issue(0, 0);
    cp_commit();
    {
        const __half* qh_g = Qhi + qrow0 * HID_DIM + h * HDIM;
#pragma unroll
        for (int i = tid; i < 128 * 8; i += 256) {
            const int r = i >> 3, c8 = (i & 7) * 8;
            const uint32_t so = (uint32_t)r * ROWB + c8 * 2;
            *(uint4*)(smc + so) = *(const uint4*)(qh_g + (size_t)r * HID_DIM + c8);
        }
    }
    __syncthreads();
    uint32_t qh[4][4];
#pragma unroll
    for (int ks = 0; ks < 4; ks++) {
        const uint32_t off = (uint32_t)(wid * 16 + lrow) * ROWB + (ks * 16 + lcol) * 2;
        ldsm_x4(qh[ks], uS + off);
    }

    float m1 = -1e30f, m2 = -1e30f, lp1 = 0.0f, lp2 = 0.0f;
    float oacc[8][4] = {};

    for (int ch = 0; ch < NCH; ch++) {
        if (ch + 1 < NCH) {
            issue(ch + 1, (ch + 1) & 1);
            cp_commit();
            cp_wait1();
        } else {
            cp_wait0();
        }
        __syncthreads();

        const uint32_t base = uS + ST0 + (uint32_t)(ch & 1) * STG;

        float sc[8][4] = {};
#pragma unroll
        for (int ks = 0; ks < 4; ks++) {
#pragma unroll
            for (int p = 0; p < 4; p++) {
                const uint32_t off =
                    (uint32_t)(p * 16 + lrow) * ROWB + (ks * 16 + lcol) * 2;
                uint32_t rh[4];
                ldsm_x4(rh, base + off);
                uint32_t b0[2] = {rh[0], rh[2]}, b1[2] = {rh[1], rh[3]};
                mma_f16(sc[2 * p], qh[ks], b0);
                mma_f16(sc[2 * p + 1], qh[ks], b1);
            }
        }

        float mx1 = m1, mx2 = m2;
#pragma unroll
        for (int nf = 0; nf < 8; nf++) {
            mx1 = fmaxf(mx1, fmaxf(sc[nf][0], sc[nf][1]));
            mx2 = fmaxf(mx2, fmaxf(sc[nf][2], sc[nf][3]));
        }
        mx1 = fmaxf(mx1, __shfl_xor_sync(0xffffffffu, mx1, 1));
        mx1 = fmaxf(mx1, __shfl_xor_sync(0xffffffffu, mx1, 2));
        mx2 = fmaxf(mx2, __shfl_xor_sync(0xffffffffu, mx2, 1));
        mx2 = fmaxf(mx2, __shfl_xor_sync(0xffffffffu, mx2, 2));
        const float a1 = __expf(m1 - mx1);
        const float a2 = __expf(m2 - mx2);
        m1 = mx1; m2 = mx2;

        float s1 = 0.0f, s2 = 0.0f;
        uint32_t pr1[8], pr2[8];
#pragma unroll
        for (int nf = 0; nf < 8; nf++) {
            const float p0 = __expf(sc[nf][0] - mx1);
            const float p1 = __expf(sc[nf][1] - mx1);
            const float p2 = __expf(sc[nf][2] - mx2);
            const float p3 = __expf(sc[nf][3] - mx2);
            s1 += p0 + p1; s2 += p2 + p3;
            pr1[nf] = pack_h2(p0, p1);
            pr2[nf] = pack_h2(p2, p3);
        }
        lp1 = lp1 * a1 + s1;
        lp2 = lp2 * a2 + s2;
#pragma unroll
        for (int nf = 0; nf < 8; nf++) {
            oacc[nf][0] *= a1; oacc[nf][1] *= a1;
            oacc[nf][2] *= a2; oacc[nf][3] *= a2;
        }

#pragma unroll
        for (int ks = 0; ks < 4; ks++) {
            uint32_t pa[4] = {pr1[2 * ks], pr2[2 * ks],
                              pr1[2 * ks + 1], pr2[2 * ks + 1]};
#pragma unroll
            for (int p = 0; p < 4; p++) {
                const uint32_t off =
                    (uint32_t)(ks * 16 + lrow) * ROWB + (p * 16 + lcol) * 2;
                uint32_t rh[4];
                ldsm_x4_t(rh, base + VHI + off);
                uint32_t b0[2] = {rh[0], rh[1]}, b1[2] = {rh[2], rh[3]};
                mma_f16(oacc[2 * p], pa, b0);
                mma_f16(oacc[2 * p + 1], pa, b1);
            }
        }
        __syncthreads();
    }

    lp1 += __shfl_xor_sync(0xffffffffu, lp1, 1);
    lp1 += __shfl_xor_sync(0xffffffffu, lp1, 2);
    lp2 += __shfl_xor_sync(0xffffffffu, lp2, 1);
    lp2 += __shfl_xor_sync(0xffffffffu, lp2, 2);
    const float i1 = 1.0f / lp1, i2 = 1.0f / lp2;

    const size_t row1 = qrow0 + wid * 16 + (lane >> 2);
    const size_t row2 = row1 + 8;
#pragma unroll
    for (int nf = 0; nf < 8; nf++) {
        const int col = h * HDIM + nf * 8 + (lane & 3) * 2;
        uint32_t hp, lp;
        split_pack_h(oacc[nf][0] * i1, oacc[nf][1] * i1, hp, lp);
        *(uint32_t*)(Ohi + row1 * HID_DIM + col) = hp;
        *(uint32_t*)(Olo + row1 * HID_DIM + col) = lp;
        split_pack_h(oacc[nf][2] * i2, oacc[nf][3] * i2, hp, lp);
        *(uint32_t*)(Ohi + row2 * HID_DIM + col) = hp;
        *(uint32_t*)(Olo + row2 * HID_DIM + col) = lp;
    }
}

static const int GEMMH_SMEM = 2 * (2 * 128 + 128) * 144;   // 110592
static const int ATTN_SMEM  = 128 * 144 + 2 * 128 * 144;   // 55296

// ---------------------------------------------------------------------------
// Launch
// ---------------------------------------------------------------------------
extern "C" void kernel_launch(void* const* d_in, const int* in_sizes, int n_in,
                              void* d_out, int out_size)
{
    const float* query = (const float*)d_in[0];
    const float* key   = (const float*)d_in[1];
    const float* value = (const float*)d_in[2];
    const float* Wq    = (const float*)d_in[3];
    const float* bq    = (const float*)d_in[4];
    const float* Wk    = (const float*)d_in[5];
    const float* bk    = (const float*)d_in[6];
    const float* Wv    = (const float*)d_in[7];
    const float* bv    = (const float*)d_in[8];
    const float* Wo    = (const float*)d_in[9];
    const float* bo    = (const float*)d_in[10];
    float* out = (float*)d_out;

    void *qh, *ql, *kh, *kl, *vh, *vl;
    void *wqh, *wkh, *wvh, *woh;
    void *qph, *kph, *vph, *oh, *ol;
    cudaGetSymbolAddress(&qh, g_qhi); cudaGetSymbolAddress(&ql, g_qlo);
    cudaGetSymbolAddress(&kh, g_khi); cudaGetSymbolAddress(&kl, g_klo);
    cudaGetSymbolAddress(&vh, g_vhi); cudaGetSymbolAddress(&vl, g_vlo);
    cudaGetSymbolAddress(&wqh, g_WqTh);
    cudaGetSymbolAddress(&wkh, g_WkTh);
    cudaGetSymbolAddress(&wvh, g_WvTh);
    cudaGetSymbolAddress(&woh, g_WoTh);
    cudaGetSymbolAddress(&qph, g_qPhi);
    cudaGetSymbolAddress(&kph, g_kPhi);
    cudaGetSymbolAddress(&vph, g_vPhi);
    cudaGetSymbolAddress(&oh, g_ohi);   cudaGetSymbolAddress(&ol, g_olo);

    cudaFuncSetAttribute((const void*)gemm_proj_all,
                         cudaFuncAttributeMaxDynamicSharedMemorySize, GEMMH_SMEM);
    cudaFuncSetAttribute((const void*)gemm_o,
                         cudaFuncAttributeMaxDynamicSharedMemorySize, GEMMH_SMEM);
    cudaFuncSetAttribute((const void*)mqa_attn_mma,
                         cudaFuncAttributeMaxDynamicSharedMemorySize, ATTN_SMEM);

    // --- prep ---
    {
        dim3 blk(32, 8);
        TH2 tqo;
        tqo.W[0] = Wq; tqo.T[0] = (__half*)wqh;
        tqo.W[1] = Wo; tqo.T[1] = (__half*)woh;
        transpose_h2<<<dim3(HID_DIM / 32, KDIM / 32, 2), blk>>>(tqo, KDIM, HID_DIM);
        TH2 tkv;
        tkv.W[0] = Wk; tkv.T[0] = (__half*)wkh;
        tkv.W[1] = Wv; tkv.T[1] = (__half*)wvh;
        transpose_h2<<<dim3(HDIM / 32, KDIM / 32, 2), blk>>>(tkv, KDIM, HDIM);

        const int n8 = MROWS * KDIM / 8;
        SR3 sr;
        sr.X[0] = (const float4*)query; sr.hi[0] = (uint4*)qh; sr.lo[0] = (uint4*)ql;
        sr.X[1] = (const float4*)key;   sr.hi[1] = (uint4*)kh; sr.lo[1] = (uint4*)kl;
        sr.X[2] = (const float4*)value; sr.hi[2] = (uint4*)vh; sr.lo[2] = (uint4*)vl;
        split_rows3<<<dim3((n8 + 255) / 256, 3), 256>>>(sr, n8);
    }
    // --- merged Q/K/V projections (2-term fp16; Q scaled 1/32) ---
    {
        ProjArgs a;
        a.qAhi = (const __half*)qh; a.qAlo = (const __half*)ql;
        a.qBh = (const __half*)wqh; a.qb = bq; a.qC = (__half*)qph;
        a.kvAhi[0] = (const __half*)kh; a.kvAlo[0] = (const __half*)kl;
        a.kvBh[0] = (const __half*)wkh; a.kvb[0] = bk; a.kvC[0] = (__half*)kph;
        a.kvAhi[1] = (const __half*)vh; a.kvAlo[1] = (const __half*)vl;
        a.kvBh[1] = (const __half*)wvh; a.kvb[1] = bv; a.kvC[1] = (__half*)vph;
        gemm_proj_all<<<dim3(HID_DIM / 128, MROWS / 128, 3), 256, GEMMH_SMEM>>>(a);
    }

    // --- tensor-core attention (pure fp16) ---
    {
        dim3 grid(SEQ / 128, NHEAD, BATCH);
        mqa_attn_mma<<<grid, 256, ATTN_SMEM>>>(
            (const __half*)qph, (const __half*)kph, (const __half*)vph,
            (__half*)oh, (__half*)ol);
    }

    // --- O-projection (2-term fp16) -> d_out ---
    gemm_o<<<dim3(IN_DIM / 128, MROWS / 128), 256, GEMMH_SMEM>>>(
        (const __half*)oh, (const __half*)ol, (const __half*)woh, bo, out);
}

// round 16
// speedup vs baseline: 1.5525x; 1.2560x over previous
#include <cuda_runtime.h>
#include <cuda_fp16.h>
#include <cstdint>

#define BATCH 2
#define SEQ 2048
#define IN_DIM 1024
#define HID_DIM 1024
#define NHEAD 16
#define HDIM 64
#define KDIM 1024
#define MROWS 4096

// ---------------------------------------------------------------------------
// Scratch (__device__ globals; allocation-free rule)
// ---------------------------------------------------------------------------
// inputs, single fp16
__device__ __half g_qin[MROWS * KDIM];
__device__ __half g_kin[MROWS * KDIM];
__device__ __half g_vin[MROWS * KDIM];
// transposed weights, single fp16 [N][K]
__device__ __half g_WqTh[HID_DIM * KDIM];
__device__ __half g_WkTh[HDIM * KDIM];
__device__ __half g_WvTh[HDIM * KDIM];
__device__ __half g_WoTh[IN_DIM * KDIM];
// projected fp16 operands for attention: Q scaled by 1/32
__device__ __half g_qPhi[MROWS * HID_DIM];
__device__ __half g_kPhi[MROWS * HDIM];
__device__ __half g_vPhi[MROWS * HDIM];
// attention output, single fp16 (A operand of O-projection)
__device__ __half g_oh[MROWS * HID_DIM];

// ---------------------------------------------------------------------------
// PTX helpers (all sm_80-era; legal in family-generic PTX)
// ---------------------------------------------------------------------------
__device__ __forceinline__ uint32_t smem_u32(const void* p) {
    uint32_t a;
    asm("{ .reg .u64 t; cvta.to.shared.u64 t, %1; cvt.u32.u64 %0, t; }"
        : "=r"(a) : "l"(p));
    return a;
}
__device__ __forceinline__ void ldsm_x4(uint32_t* r, uint32_t addr) {
    asm volatile("ldmatrix.sync.aligned.m8n8.x4.shared.b16 {%0,%1,%2,%3}, [%4];"
                 : "=r"(r[0]), "=r"(r[1]), "=r"(r[2]), "=r"(r[3]) : "r"(addr));
}
__device__ __forceinline__ void ldsm_x4_t(uint32_t* r, uint32_t addr) {
    asm volatile("ldmatrix.sync.aligned.m8n8.x4.trans.shared.b16 {%0,%1,%2,%3}, [%4];"
                 : "=r"(r[0]), "=r"(r[1]), "=r"(r[2]), "=r"(r[3]) : "r"(addr));
}
__device__ __forceinline__ void mma_f16(float* d, const uint32_t* a,
                                        const uint32_t* b) {
    asm volatile(
        "mma.sync.aligned.m16n8k16.row.col.f32.f16.f16.f32 "
        "{%0,%1,%2,%3}, {%4,%5,%6,%7}, {%8,%9}, {%0,%1,%2,%3};"
        : "+f"(d[0]), "+f"(d[1]), "+f"(d[2]), "+f"(d[3])
        : "r"(a[0]), "r"(a[1]), "r"(a[2]), "r"(a[3]), "r"(b[0]), "r"(b[1]));
}
__device__ __forceinline__ void cp16(uint32_t smem, const void* g) {
    asm volatile("cp.async.cg.shared.global [%0], [%1], 16;"
                 :: "r"(smem), "l"(g));
}
__device__ __forceinline__ void cp_commit() {
    asm volatile("cp.async.commit_group;" ::: "memory");
}
__device__ __forceinline__ void cp_wait1() {
    asm volatile("cp.async.wait_group 1;" ::: "memory");
}
__device__ __forceinline__ void cp_wait0() {
    asm volatile("cp.async.wait_group 0;" ::: "memory");
}
__device__ __forceinline__ uint32_t pack_h2(float e, float o) {
    __half2 P(__float2half_rn(e), __float2half_rn(o));
    return *reinterpret_cast<uint32_t*>(&P);
}

// ---------------------------------------------------------------------------
// Prep kernels
// ---------------------------------------------------------------------------
// transpose fp32 W[K,N] -> single fp16 T[N,K]; grid.z picks one of two weights
struct TH2 { const float* W[2]; __half* T[2]; };
__global__ void transpose_h2(TH2 a, int K, int N)
{
    __shared__ float t[32][33];
    const int z = blockIdx.z;
    const int n0 = blockIdx.x * 32, k0 = blockIdx.y * 32;
    const int tx = threadIdx.x, ty = threadIdx.y;
#pragma unroll
    for (int i = 0; i < 32; i += 8)
        t[ty + i][tx] = a.W[z][(size_t)(k0 + ty + i) * N + n0 + tx];
    __syncthreads();
#pragma unroll
    for (int i = 0; i < 32; i += 8)
        a.T[z][(size_t)(n0 + ty + i) * K + k0 + tx] = __float2half_rn(t[tx][ty + i]);
}

// vectorized fp32 -> fp16 convert: 8 fp32 in (2x float4), uint4 out
struct CV3 { const float4* X[3]; uint4* Y[3]; };
__global__ void convert_rows3(CV3 a, int n8)
{
    const int z = blockIdx.y;
    const int i = blockIdx.x * blockDim.x + threadIdx.x;
    if (i < n8) {
        const float4 v0 = a.X[z][2 * i];
        const float4 v1 = a.X[z][2 * i + 1];
        uint4 H;
        H.x = pack_h2(v0.x, v0.y);
        H.y = pack_h2(v0.z, v0.w);
        H.z = pack_h2(v1.x, v1.y);
        H.w = pack_h2(v1.z, v1.w);
        a.Y[z][i] = H;
    }
}

// ---------------------------------------------------------------------------
// 1-term fp16 GEMM core: C[M,N] = A[M,K] @ B[N,K]^T + bias
// cp.async double-buffered, K-chunk 64.
// EPI=0: fp32 out.  EPI=2: fp16 single out, scaled.
// ---------------------------------------------------------------------------
template <int BM, int BN, int EPI>
__device__ __forceinline__ void gemm_core_h1(
    const __half* A, const __half* Bh,
    const float* bias, float* C, __half* Chi,
    float scale, int Ntot, int m0, int n0, char* smem)
{
    constexpr int MF = BM / 64;
    constexpr int WN = BN / 2;
    constexpr int NF = WN / 8;
    constexpr uint32_t ROWB = 144;
    constexpr uint32_t OBH = BM * ROWB;
    constexpr uint32_t STAGE = (BM + BN) * ROWB;
    constexpr int NCH = KDIM / 64;

    const uint32_t uS = smem_u32(smem);
    const int tid = threadIdx.x;
    const int wid = tid >> 5, lane = tid & 31;
    const int warp_m = wid & 3, warp_n = wid >> 2;
    const int lrow = lane & 15;
    const int lcol = (lane >> 4) * 8;

    const __half* a_g = A + (size_t)m0 * KDIM;
    const __half* b_g = Bh + (size_t)n0 * KDIM;

    auto issue = [&](int ch, int buf) {
        const int k0 = ch * 64;
        const uint32_t base = uS + (uint32_t)buf * STAGE;
#pragma unroll
        for (int i = tid; i < BM * 8; i += 256) {
            const int r = i >> 3, c8 = (i & 7) * 8;
            cp16(base + (uint32_t)r * ROWB + c8 * 2,
                 a_g + (size_t)r * KDIM + k0 + c8);
        }
#pragma unroll
        for (int i = tid; i < BN * 8; i += 256) {
            const int r = i >> 3, c8 = (i & 7) * 8;
            cp16(base + OBH + (uint32_t)r * ROWB + c8 * 2,
                 b_g + (size_t)r * KDIM + k0 + c8);
        }
    };

    float acc[MF][NF][4] = {};

    issue(0, 0);
    cp_commit();

    for (int ch = 0; ch < NCH; ch++) {
        if (ch + 1 < NCH) {
            issue(ch + 1, (ch + 1) & 1);
            cp_commit();
            cp_wait1();
        } else {
            cp_wait0();
        }
        __syncthreads();

        const uint32_t base = uS + (uint32_t)(ch & 1) * STAGE;
#pragma unroll
        for (int ks = 0; ks < 4; ks++) {
            const int kk = ks * 16 + lcol;
            uint32_t ah[MF][4];
#pragma unroll
            for (int mf = 0; mf < MF; mf++) {
                const int row = warp_m * (BM / 4) + mf * 16 + lrow;
                ldsm_x4(ah[mf], base + (uint32_t)row * ROWB + kk * 2);
            }
            uint32_t bh[NF][2];
#pragma unroll
            for (int p = 0; p < NF / 2; p++) {
                const int row = warp_n * WN + p * 16 + lrow;
                uint32_t r4[4];
                ldsm_x4(r4, base + OBH + (uint32_t)row * ROWB + kk * 2);
                bh[2 * p][0] = r4[0]; bh[2 * p][1] = r4[2];
                bh[2 * p + 1][0] = r4[1]; bh[2 * p + 1][1] = r4[3];
            }
#pragma unroll
            for (int mf = 0; mf < MF; mf++)
#pragma unroll
                for (int nf = 0; nf < NF; nf++)
                    mma_f16(acc[mf][nf], ah[mf], bh[nf]);
        }
        __syncthreads();
    }

    const int gid = lane >> 2, t4 = lane & 3;
#pragma unroll
    for (int mf = 0; mf < MF; mf++) {
        const int row = m0 + warp_m * (BM / 4) + mf * 16 + gid;
#pragma unroll
        for (int nf = 0; nf < NF; nf++) {
            const int col = n0 + warp_n * WN + nf * 8 + t4 * 2;
            const float b0 = bias[col], b1 = bias[col + 1];
            if (EPI == 0) {
                float2 o0 = make_float2(acc[mf][nf][0] + b0, acc[mf][nf][1] + b1);
                float2 o1 = make_float2(acc[mf][nf][2] + b0, acc[mf][nf][3] + b1);
                *(float2*)(C + (size_t)row * Ntot + col) = o0;
                *(float2*)(C + (size_t)(row + 8) * Ntot + col) = o1;
            } else {
                *(uint32_t*)(Chi + (size_t)row * Ntot + col) =
                    pack_h2((acc[mf][nf][0] + b0) * scale,
                            (acc[mf][nf][1] + b1) * scale);
                *(uint32_t*)(Chi + (size_t)(row + 8) * Ntot + col) =
                    pack_h2((acc[mf][nf][2] + b0) * scale,
                            (acc[mf][nf][3] + b1) * scale);
            }
        }
    }
}

// ---------------------------------------------------------------------------
// Merged Q/K/V projection launch. grid (8, 32, 3):
//   z=0: Q-proj 128x128 tiles; z=1/2: K/V-proj 64x64 tiles (64 CTAs active)
// ---------------------------------------------------------------------------
struct ProjArgs {
    const __half *qA, *qBh; const float* qb; __half* qC;
    const __half *kvA[2], *kvBh[2];
    const float* kvb[2]; __half* kvC[2];
};
__global__ __launch_bounds__(256) void gemm_proj_all(ProjArgs a)
{
    extern __shared__ char smem[];
    const int z = blockIdx.z;
    if (z == 0) {
        gemm_core_h1<128, 128, 2>(a.qA, a.qBh, a.qb,
                                  nullptr, a.qC, 1.0f / 32.0f, HID_DIM,
                                  blockIdx.y * 128, blockIdx.x * 128, smem);
    } else {
        const int id = blockIdx.y * 8 + blockIdx.x;   // 0..255
        if (id >= MROWS / 64) return;                 // 64 active
        const int s = z - 1;
        gemm_core_h1<64, 64, 2>(a.kvA[s], a.kvBh[s],
                                a.kvb[s], nullptr, a.kvC[s], 1.0f, HDIM,
                                id * 64, 0, smem);
    }
}

// O-projection: 1-term fp16, fp32 epilogue -> d_out
__global__ __launch_bounds__(256) void gemm_o(
    const __half* __restrict__ A, const __half* __restrict__ Bh,
    const float* __restrict__ bias, float* __restrict__ C)
{
    extern __shared__ char smem[];
    gemm_core_h1<128, 128, 0>(A, Bh, bias, C, nullptr, 1.0f, IN_DIM,
                              blockIdx.y * 128, blockIdx.x * 128, smem);
}

// ---------------------------------------------------------------------------
// Tensor-core MQA attention, pure single-fp16:
//   scores = Q·K (1 term);  PV = P·V (1 term)
// Epilogue: single fp16 normalized output.
// ---------------------------------------------------------------------------
__global__ __launch_bounds__(256) void mqa_attn_mma(
    const __half* __restrict__ Qhi,
    const __half* __restrict__ Khi, const __half* __restrict__ Vhi,
    __half* __restrict__ Oh)
{
    constexpr uint32_t ROWB = 144;
    constexpr uint32_t ST0 = 128 * ROWB;
    constexpr uint32_t STG = 128 * ROWB;
    constexpr uint32_t VHI = 64 * ROWB;
    constexpr int NCH = SEQ / 64;

    extern __shared__ char smc[];
    const uint32_t uS = smem_u32(smc);

    const int tid = threadIdx.x, wid = tid >> 5, lane = tid & 31;
    const int h = blockIdx.y, b = blockIdx.z;
    const int q0 = blockIdx.x * 128;
    const size_t qrow0 = (size_t)b * SEQ + q0;
    const int lrow = lane & 15;
    const int lcol = (lane >> 4) * 8;

    const __half* kh_g = Khi + (size_t)b * SEQ * HDIM;
    const __half* vh_g = Vhi + (size_t)b * SEQ * HDIM;

    auto issue = [&](int ch, int buf) {
        const int k0 = ch * 64;
        const uint32_t base = uS + ST0 + (uint32_t)buf * STG;
#pragma unroll
        for (int i = tid; i < 64 * 8; i += 256) {
            const int r = i >> 3, c8 = (i & 7) * 8;
            const uint32_t so = (uint32_t)r * ROWB + c8 * 2;
            const size_t g = (size_t)(k0 + r) * HDIM + c8;
            cp16(base + so, kh_g + g);
            cp16(base + VHI + so, vh_g + g);
        }
    };

    issue(0, 0);
    cp_commit();
    {
        const __half* qh_g = Qhi + qrow0 * HID_DIM + h * HDIM;
#pragma unroll
        for (int i = tid; i < 128 * 8; i += 256) {
            const int r = i >> 3, c8 = (i & 7) * 8;
            const uint32_t so = (uint32_t)r * ROWB + c8 * 2;
            *(uint4*)(smc + so) = *(const uint4*)(qh_g + (size_t)r * HID_DIM + c8);
        }
    }
    __syncthreads();
    uint32_t qh[4][4];
#pragma unroll
    for (int ks = 0; ks < 4; ks++) {
        const uint32_t off = (uint32_t)(wid * 16 + lrow) * ROWB + (ks * 16 + lcol) * 2;
        ldsm_x4(qh[ks], uS + off);
    }

    float m1 = -1e30f, m2 = -1e30f, lp1 = 0.0f, lp2 = 0.0f;
    float oacc[8][4] = {};

    for (int ch = 0; ch < NCH; ch++) {
        if (ch + 1 < NCH) {
            issue(ch + 1, (ch + 1) & 1);
            cp_commit();
            cp_wait1();
        } else {
            cp_wait0();
        }
        __syncthreads();

        const uint32_t base = uS + ST0 + (uint32_t)(ch & 1) * STG;

        float sc[8][4] = {};
#pragma unroll
        for (int ks = 0; ks < 4; ks++) {
#pragma unroll
            for (int p = 0; p < 4; p++) {
                const uint32_t off =
                    (uint32_t)(p * 16 + lrow) * ROWB + (ks * 16 + lcol) * 2;
                uint32_t rh[4];
                ldsm_x4(rh, base + off);
                uint32_t b0[2] = {rh[0], rh[2]}, b1[2] = {rh[1], rh[3]};
                mma_f16(sc[2 * p], qh[ks], b0);
                mma_f16(sc[2 * p + 1], qh[ks], b1);
            }
        }

        float mx1 = m1, mx2 = m2;
#pragma unroll
        for (int nf = 0; nf < 8; nf++) {
            mx1 = fmaxf(mx1, fmaxf(sc[nf][0], sc[nf][1]));
            mx2 = fmaxf(mx2, fmaxf(sc[nf][2], sc[nf][3]));
        }
        mx1 = fmaxf(mx1, __shfl_xor_sync(0xffffffffu, mx1, 1));
        mx1 = fmaxf(mx1, __shfl_xor_sync(0xffffffffu, mx1, 2));
        mx2 = fmaxf(mx2, __shfl_xor_sync(0xffffffffu, mx2, 1));
        mx2 = fmaxf(mx2, __shfl_xor_sync(0xffffffffu, mx2, 2));
        const float a1 = __expf(m1 - mx1);
        const float a2 = __expf(m2 - mx2);
        m1 = mx1; m2 = mx2;

        float s1 = 0.0f, s2 = 0.0f;
        uint32_t pr1[8], pr2[8];
#pragma unroll
        for (int nf = 0; nf < 8; nf++) {
            const float p0 = __expf(sc[nf][0] - mx1);
            const float p1 = __expf(sc[nf][1] - mx1);
            const float p2 = __expf(sc[nf][2] - mx2);
            const float p3 = __expf(sc[nf][3] - mx2);
            s1 += p0 + p1; s2 += p2 + p3;
            pr1[nf] = pack_h2(p0, p1);
            pr2[nf] = pack_h2(p2, p3);
        }
        lp1 = lp1 * a1 + s1;
        lp2 = lp2 * a2 + s2;
#pragma unroll
        for (int nf = 0; nf < 8; nf++) {
            oacc[nf][0] *= a1; oacc[nf][1] *= a1;
            oacc[nf][2] *= a2; oacc[nf][3] *= a2;
        }

#pragma unroll
        for (int ks = 0; ks < 4; ks++) {
            uint32_t pa[4] = {pr1[2 * ks], pr2[2 * ks],
                              pr1[2 * ks + 1], pr2[2 * ks + 1]};
#pragma unroll
            for (int p = 0; p < 4; p++) {
                const uint32_t off =
                    (uint32_t)(ks * 16 + lrow) * ROWB + (p * 16 + lcol) * 2;
                uint32_t rh[4];
                ldsm_x4_t(rh, base + VHI + off);
                uint32_t b0[2] = {rh[0], rh[1]}, b1[2] = {rh[2], rh[3]};
                mma_f16(oacc[2 * p], pa, b0);
                mma_f16(oacc[2 * p + 1], pa, b1);
            }
        }
        __syncthreads();
    }

    lp1 += __shfl_xor_sync(0xffffffffu, lp1, 1);
    lp1 += __shfl_xor_sync(0xffffffffu, lp1, 2);
    lp2 += __shfl_xor_sync(0xffffffffu, lp2, 1);
    lp2 += __shfl_xor_sync(0xffffffffu, lp2, 2);
    const float i1 = 1.0f / lp1, i2 = 1.0f / lp2;

    const size_t row1 = qrow0 + wid * 16 + (lane >> 2);
    const size_t row2 = row1 + 8;
#pragma unroll
    for (int nf = 0; nf < 8; nf++) {
        const int col = h * HDIM + nf * 8 + (lane & 3) * 2;
        *(uint32_t*)(Oh + row1 * HID_DIM + col) =
            pack_h2(oacc[nf][0] * i1, oacc[nf][1] * i1);
        *(uint32_t*)(Oh + row2 * HID_DIM + col) =
            pack_h2(oacc[nf][2] * i2, oacc[nf][3] * i2);
    }
}

static const int GEMMH_SMEM = 2 * (128 + 128) * 144;       // 73728
static const int ATTN_SMEM  = 128 * 144 + 2 * 128 * 144;   // 55296

// ---------------------------------------------------------------------------
// Launch
// ---------------------------------------------------------------------------
extern "C" void kernel_launch(void* const* d_in, const int* in_sizes, int n_in,
                              void* d_out, int out_size)
{
    const float* query = (const float*)d_in[0];
    const float* key   = (const float*)d_in[1];
    const float* value = (const float*)d_in[2];
    const float* Wq    = (const float*)d_in[3];
    const float* bq    = (const float*)d_in[4];
    const float* Wk    = (const float*)d_in[5];
    const float* bk    = (const float*)d_in[6];
    const float* Wv    = (const float*)d_in[7];
    const float* bv    = (const float*)d_in[8];
    const float* Wo    = (const float*)d_in[9];
    const float* bo    = (const float*)d_in[10];
    float* out = (float*)d_out;

    void *qi, *ki, *vi;
    void *wqh, *wkh, *wvh, *woh;
    void *qph, *kph, *vph, *oh;
    cudaGetSymbolAddress(&qi, g_qin);
    cudaGetSymbolAddress(&ki, g_kin);
    cudaGetSymbolAddress(&vi, g_vin);
    cudaGetSymbolAddress(&wqh, g_WqTh);
    cudaGetSymbolAddress(&wkh, g_WkTh);
    cudaGetSymbolAddress(&wvh, g_WvTh);
    cudaGetSymbolAddress(&woh, g_WoTh);
    cudaGetSymbolAddress(&qph, g_qPhi);
    cudaGetSymbolAddress(&kph, g_kPhi);
    cudaGetSymbolAddress(&vph, g_vPhi);
    cudaGetSymbolAddress(&oh, g_oh);

    cudaFuncSetAttribute((const void*)gemm_proj_all,
                         cudaFuncAttributeMaxDynamicSharedMemorySize, GEMMH_SMEM);
    cudaFuncSetAttribute((const void*)gemm_o,
                         cudaFuncAttributeMaxDynamicSharedMemorySize, GEMMH_SMEM);
    cudaFuncSetAttribute((const void*)mqa_attn_mma,
                         cudaFuncAttributeMaxDynamicSharedMemorySize, ATTN_SMEM);

    // --- prep ---
    {
        dim3 blk(32, 8);
        TH2 tqo;
        tqo.W[0] = Wq; tqo.T[0] = (__half*)wqh;
        tqo.W[1] = Wo; tqo.T[1] = (__half*)woh;
        transpose_h2<<<dim3(HID_DIM / 32, KDIM / 32, 2), blk>>>(tqo, KDIM, HID_DIM);
        TH2 tkv;
        tkv.W[0] = Wk; tkv.T[0] = (__half*)wkh;
        tkv.W[1] = Wv; tkv.T[1] = (__half*)wvh;
        transpose_h2<<<dim3(HDIM / 32, KDIM / 32, 2), blk>>>(tkv, KDIM, HDIM);

        const int n8 = MROWS * KDIM / 8;
        CV3 cv;
        cv.X[0] = (const float4*)query; cv.Y[0] = (uint4*)qi;
        cv.X[1] = (const float4*)key;   cv.Y[1] = (uint4*)ki;
        cv.X[2] = (const float4*)value; cv.Y[2] = (uint4*)vi;
        convert_rows3<<<dim3((n8 + 255) / 256, 3), 256>>>(cv, n8);
    }
    // --- merged Q/K/V projections (1-term fp16; Q scaled 1/32) ---
    {
        ProjArgs a;
        a.qA = (const __half*)qi; a.qBh = (const __half*)wqh;
        a.qb = bq; a.qC = (__half*)qph;
        a.kvA[0] = (const __half*)ki; a.kvBh[0] = (const __half*)wkh;
        a.kvb[0] = bk; a.kvC[0] = (__half*)kph;
        a.kvA[1] = (const __half*)vi; a.kvBh[1] = (const __half*)wvh;
        a.kvb[1] = bv; a.kvC[1] = (__half*)vph;
        gemm_proj_all<<<dim3(HID_DIM / 128, MROWS / 128, 3), 256, GEMMH_SMEM>>>(a);
    }

    // --- tensor-core attention (pure fp16) ---
    {
        dim3 grid(SEQ / 128, NHEAD, BATCH);
        mqa_attn_mma<<<grid, 256, ATTN_SMEM>>>(
            (const __half*)qph, (const __half*)kph, (const __half*)vph,
            (__half*)oh);
    }

    // --- O-projection (1-term fp16) -> d_out ---
    gemm_o<<<dim3(IN_DIM / 128, MROWS / 128), 256, GEMMH_SMEM>>>(
        (const __half*)oh, (const __half*)woh, bo, out);
}